// round 2
// baseline (speedup 1.0000x reference)
#include <cuda_runtime.h>
#include <math.h>

// Problem constants
#define SEQ   512
#define BATCH 64
#define DIN   1024
#define DH    1024
#define NG    4096              // 4 gates * DH, reordered r = j*4 + g  (g: 0=f,1=i,2=g,3=o)
#define M_TOT (SEQ * BATCH)     // 32768

// ---------------- device scratch (no allocations allowed) ----------------
__device__ float g_Wx[NG * DIN];             // 16.8 MB  (x-part of weights, row-major [r][k])
__device__ float g_Wh[NG * DH];              // 16.8 MB  (h-part of weights, row-major [r][k])
__device__ float g_bias[NG];
__device__ float g_pre[(size_t)M_TOT * NG];  // 512 MB   pre[t*64+b][r] = x@Wx^T + bias
__device__ float g_c[BATCH * DH];            // cell state
__device__ float g_h0[BATCH * DH];           // zero h for t=0

// ---------------- prep: reorder weights, biases, zero state ----------------
__global__ void prep_kernel(const float* __restrict__ Wf, const float* __restrict__ bf,
                            const float* __restrict__ Wi, const float* __restrict__ bi,
                            const float* __restrict__ Wg, const float* __restrict__ bg,
                            const float* __restrict__ Wo, const float* __restrict__ bo) {
    int idx    = blockIdx.x * blockDim.x + threadIdx.x;
    int stride = gridDim.x * blockDim.x;
    const int total = NG * 2048;
    for (int i = idx; i < total; i += stride) {
        int r = i >> 11;          // / 2048
        int k = i & 2047;
        int j = r >> 2;
        int g = r & 3;
        const float* W = (g == 0) ? Wf : (g == 1) ? Wi : (g == 2) ? Wg : Wo;
        float v = W[j * 2048 + k];
        if (k < DIN) g_Wx[r * DIN + k] = v;
        else         g_Wh[r * DH + (k - DIN)] = v;
    }
    for (int i = idx; i < NG; i += stride) {
        int j = i >> 2;
        int g = i & 3;
        const float* b = (g == 0) ? bf : (g == 1) ? bi : (g == 2) ? bg : bo;
        g_bias[i] = b[j];
    }
    for (int i = idx; i < BATCH * DH; i += stride) {
        g_c[i]  = 0.0f;
        g_h0[i] = 0.0f;
    }
}

// ---------------- input projection GEMM: pre = X @ Wx^T + bias ----------------
// M=32768, N=4096, K=1024. A row-major [M][K], B row-major [N][K] (both K-major).
#define BM 128
#define BN 128
#define BK 16

__global__ __launch_bounds__(256) void xproj_kernel(const float* __restrict__ X) {
    __shared__ float As[BK][BM];
    __shared__ float Bs[BK][BN];

    const int bm  = blockIdx.y * BM;
    const int bn  = blockIdx.x * BN;
    const int tid = threadIdx.x;
    const int tx  = tid & 15;   // n tile: n = tx*8
    const int ty  = tid >> 4;   // m tile: m = ty*8

    // loader mapping: 128 rows x 16 k-floats = 512 float4; 256 threads -> 2 float4 each
    const int lrow = tid >> 1;
    const int lseg = (tid & 1) * 8;

    float acc[8][8];
#pragma unroll
    for (int i = 0; i < 8; i++)
#pragma unroll
        for (int j = 0; j < 8; j++) acc[i][j] = 0.0f;

    for (int k0 = 0; k0 < DIN; k0 += BK) {
        const float* Ap = X    + (size_t)(bm + lrow) * DIN + k0 + lseg;
        const float* Bp = g_Wx + (size_t)(bn + lrow) * DIN + k0 + lseg;
        float4 a0 = *(const float4*)(Ap);
        float4 a1 = *(const float4*)(Ap + 4);
        float4 b0 = *(const float4*)(Bp);
        float4 b1 = *(const float4*)(Bp + 4);
        __syncthreads();   // previous tile's compute done before overwrite
        As[lseg + 0][lrow] = a0.x; As[lseg + 1][lrow] = a0.y;
        As[lseg + 2][lrow] = a0.z; As[lseg + 3][lrow] = a0.w;
        As[lseg + 4][lrow] = a1.x; As[lseg + 5][lrow] = a1.y;
        As[lseg + 6][lrow] = a1.z; As[lseg + 7][lrow] = a1.w;
        Bs[lseg + 0][lrow] = b0.x; Bs[lseg + 1][lrow] = b0.y;
        Bs[lseg + 2][lrow] = b0.z; Bs[lseg + 3][lrow] = b0.w;
        Bs[lseg + 4][lrow] = b1.x; Bs[lseg + 5][lrow] = b1.y;
        Bs[lseg + 6][lrow] = b1.z; Bs[lseg + 7][lrow] = b1.w;
        __syncthreads();
#pragma unroll
        for (int kk = 0; kk < BK; kk++) {
            float a[8], b[8];
            *(float4*)(a)     = *(const float4*)&As[kk][ty * 8];
            *(float4*)(a + 4) = *(const float4*)&As[kk][ty * 8 + 4];
            *(float4*)(b)     = *(const float4*)&Bs[kk][tx * 8];
            *(float4*)(b + 4) = *(const float4*)&Bs[kk][tx * 8 + 4];
#pragma unroll
            for (int i = 0; i < 8; i++)
#pragma unroll
                for (int j = 0; j < 8; j++) acc[i][j] += a[i] * b[j];
        }
    }

    // epilogue: add bias, store
#pragma unroll
    for (int i = 0; i < 8; i++) {
        int m = bm + ty * 8 + i;
        float* outp = g_pre + (size_t)m * NG + bn + tx * 8;
        const float* bp = g_bias + bn + tx * 8;
        float4 v0, v1;
        v0.x = acc[i][0] + bp[0]; v0.y = acc[i][1] + bp[1];
        v0.z = acc[i][2] + bp[2]; v0.w = acc[i][3] + bp[3];
        v1.x = acc[i][4] + bp[4]; v1.y = acc[i][5] + bp[5];
        v1.z = acc[i][6] + bp[6]; v1.w = acc[i][7] + bp[7];
        *(float4*)(outp)     = v0;
        *(float4*)(outp + 4) = v1;
    }
}

// ---------------- per-step recurrent kernel ----------------
// Each CTA owns SN=32 consecutive reordered gate-rows = 8 j-values * 4 gates,
// computes z = pre + h_prev @ Wh^T for tile (64 batch x 32 rows), then does the
// gate nonlinearity + c/h update for its 8 j-values locally. No cross-CTA deps.
#define SN  32
#define SBK 16

__global__ __launch_bounds__(256) void step_kernel(const float* __restrict__ h_prev_in,
                                                   float* __restrict__ out_h,
                                                   int t) {
    __shared__ float Hs[SBK][BATCH];   // h transposed tile
    __shared__ float Ws[SBK][SN];      // W transposed tile
    __shared__ float Zs[BATCH][SN];    // preactivations

    const float* h_prev = (h_prev_in == nullptr) ? g_h0 : h_prev_in;
    const float* pre_t  = g_pre + (size_t)t * BATCH * NG;

    const int r0  = blockIdx.x * SN;
    const int tid = threadIdx.x;
    const int tx  = tid & 15;   // n = tx*2
    const int ty  = tid >> 4;   // m = ty*4

    float acc[4][2] = {{0.f, 0.f}, {0.f, 0.f}, {0.f, 0.f}, {0.f, 0.f}};

    const int hrow = tid >> 2;           // 0..63
    const int hseg = (tid & 3) * 4;      // 0,4,8,12
    const int wrow = tid >> 2;           // (valid for tid<128 -> 0..31)
    const int wseg = (tid & 3) * 4;

    for (int k0 = 0; k0 < DH; k0 += SBK) {
        float4 hv = *(const float4*)(h_prev + hrow * DH + k0 + hseg);
        float4 wv = make_float4(0.f, 0.f, 0.f, 0.f);
        if (tid < 128)
            wv = *(const float4*)(g_Wh + (size_t)(r0 + wrow) * DH + k0 + wseg);
        __syncthreads();
        Hs[hseg + 0][hrow] = hv.x; Hs[hseg + 1][hrow] = hv.y;
        Hs[hseg + 2][hrow] = hv.z; Hs[hseg + 3][hrow] = hv.w;
        if (tid < 128) {
            Ws[wseg + 0][wrow] = wv.x; Ws[wseg + 1][wrow] = wv.y;
            Ws[wseg + 2][wrow] = wv.z; Ws[wseg + 3][wrow] = wv.w;
        }
        __syncthreads();
#pragma unroll
        for (int kk = 0; kk < SBK; kk++) {
            float a[4];
            *(float4*)a = *(const float4*)&Hs[kk][ty * 4];
            float b0 = Ws[kk][tx * 2];
            float b1 = Ws[kk][tx * 2 + 1];
#pragma unroll
            for (int i = 0; i < 4; i++) {
                acc[i][0] += a[i] * b0;
                acc[i][1] += a[i] * b1;
            }
        }
    }

    // z = acc + pre  -> shared
#pragma unroll
    for (int i = 0; i < 4; i++) {
        int b = ty * 4 + i;
        const float* pp = pre_t + (size_t)b * NG + r0 + tx * 2;
        Zs[b][tx * 2 + 0] = acc[i][0] + pp[0];
        Zs[b][tx * 2 + 1] = acc[i][1] + pp[1];
    }
    __syncthreads();

    // gate update: 64 batch x 8 j = 512 cells, 2 per thread
    for (int cell = tid; cell < BATCH * 8; cell += 256) {
        int b  = cell >> 3;
        int jl = cell & 7;
        int j  = (r0 >> 2) + jl;     // global hidden index
        float zf = Zs[b][jl * 4 + 0];
        float zi = Zs[b][jl * 4 + 1];
        float zg = Zs[b][jl * 4 + 2];
        float zo = Zs[b][jl * 4 + 3];
        float f  = 1.0f / (1.0f + expf(-zf));
        float ii = 1.0f / (1.0f + expf(-zi));
        float gg = tanhf(zg);
        float oo = 1.0f / (1.0f + expf(-zo));
        float c  = f * g_c[b * DH + j] + ii * gg;
        g_c[b * DH + j] = c;
        out_h[b * DH + j] = oo * tanhf(c);
    }
}

// ---------------- final: append h_n and c_n after outputs ----------------
__global__ void final_kernel(float* __restrict__ out) {
    int i = blockIdx.x * blockDim.x + threadIdx.x;
    if (i < BATCH * DH) {
        const size_t outs = (size_t)SEQ * BATCH * DH;
        out[outs + i]              = out[(size_t)(SEQ - 1) * BATCH * DH + i];  // h_n
        out[outs + BATCH * DH + i] = g_c[i];                                   // c_n
    }
}

// ---------------- launch ----------------
extern "C" void kernel_launch(void* const* d_in, const int* in_sizes, int n_in,
                              void* d_out, int out_size) {
    const float* X  = (const float*)d_in[0];
    const float* Wf = (const float*)d_in[1];
    const float* bf = (const float*)d_in[2];
    const float* Wi = (const float*)d_in[3];
    const float* bi = (const float*)d_in[4];
    const float* Wg = (const float*)d_in[5];
    const float* bg = (const float*)d_in[6];
    const float* Wo = (const float*)d_in[7];
    const float* bo = (const float*)d_in[8];
    float* out = (float*)d_out;

    prep_kernel<<<1024, 256>>>(Wf, bf, Wi, bi, Wg, bg, Wo, bo);

    dim3 gA(NG / BN, M_TOT / BM);   // (32, 256)
    xproj_kernel<<<gA, 256>>>(X);

    for (int t = 0; t < SEQ; t++) {
        const float* hp = (t == 0) ? nullptr : (out + (size_t)(t - 1) * BATCH * DH);
        step_kernel<<<NG / SN, 256>>>(hp, out + (size_t)t * BATCH * DH, t);
    }

    final_kernel<<<(BATCH * DH + 255) / 256, 256>>>(out);
}

// round 4
// speedup vs baseline: 1.9342x; 1.9342x over previous
#include <cuda_runtime.h>
#include <cuda_bf16.h>
#include <stdint.h>

// ---------------- problem constants ----------------
#define SEQ   512
#define BATCH 64
#define DIN   1024
#define DH    1024
#define NG    4096            // 4 gates * DH, reordered r = j*4 + g
#define KP    3072            // split-K: A=[hi|hi|lo], B=[hi|lo|hi]
#define MTOT  (SEQ * BATCH)

// ---------------- device scratch ----------------
__device__ __align__(16) __nv_bfloat16 g_Wx[(size_t)NG * KP];     // 25 MB
__device__ __align__(16) __nv_bfloat16 g_Wh[(size_t)NG * KP];     // 25 MB
__device__ __align__(16) __nv_bfloat16 g_Xs[(size_t)MTOT * KP];   // 192 MB
__device__ __align__(16) __nv_bfloat16 g_hs[2][BATCH * KP];       // h split ping-pong
__device__ float g_bias[NG];
__device__ float g_pre[(size_t)SEQ * NG * BATCH];                 // 512 MB  pre[t][r][b]
__device__ float g_c[BATCH * DH];                                 // cell state [b][j]

// ---------------- asm helpers (baseline PTX only: sm_80-era ops) ----------------
__device__ __forceinline__ uint32_t smem_u32(const void* p) {
    uint32_t a;
    asm("{ .reg .u64 t; cvta.to.shared.u64 t, %1; cvt.u32.u64 %0, t; }" : "=r"(a) : "l"(p));
    return a;
}
#define CP16(dst, src) asm volatile("cp.async.cg.shared.global [%0], [%1], 16;" :: "r"(dst), "l"(src))
#define CP_COMMIT()    asm volatile("cp.async.commit_group;" ::: "memory")
#define CP_WAIT(n)     asm volatile("cp.async.wait_group %0;" :: "n"(n) : "memory")

#define LDSM4(r0, r1, r2, r3, a) \
    asm volatile("ldmatrix.sync.aligned.m8n8.x4.shared.b16 {%0,%1,%2,%3}, [%4];" \
                 : "=r"(r0), "=r"(r1), "=r"(r2), "=r"(r3) : "r"(a))

#define MMA(d, a0, a1, a2, a3, b0, b1) \
    asm volatile("mma.sync.aligned.m16n8k16.row.col.f32.bf16.bf16.f32 " \
                 "{%0,%1,%2,%3}, {%4,%5,%6,%7}, {%8,%9}, {%0,%1,%2,%3};" \
                 : "+f"((d)[0]), "+f"((d)[1]), "+f"((d)[2]), "+f"((d)[3]) \
                 : "r"(a0), "r"(a1), "r"(a2), "r"(a3), "r"(b0), "r"(b1))

__device__ __forceinline__ float sigf(float x) { return 1.0f / (1.0f + __expf(-x)); }
__device__ __forceinline__ float tanhfast(float x) { return 1.0f - 2.0f / (__expf(2.0f * x) + 1.0f); }

// ---------------- prep: split weights/bias, zero states ----------------
__global__ void prep_kernel(const float* __restrict__ Wf, const float* __restrict__ bf,
                            const float* __restrict__ Wi, const float* __restrict__ bi,
                            const float* __restrict__ Wg, const float* __restrict__ bg,
                            const float* __restrict__ Wo, const float* __restrict__ bo) {
    int idx = blockIdx.x * blockDim.x + threadIdx.x;
    int stride = gridDim.x * blockDim.x;
    for (int i = idx; i < NG * 512; i += stride) {
        int r = i >> 9;
        int k4 = (i & 511) * 4;
        int j = r >> 2, g = r & 3;
        const float* W = (g == 0) ? Wf : (g == 1) ? Wi : (g == 2) ? Wg : Wo;
        float4 v = *(const float4*)(W + (size_t)j * 2048 + k4);
        float vv[4] = {v.x, v.y, v.z, v.w};
        union { __nv_bfloat16 h[4]; uint2 u; } hi4, lo4;
#pragma unroll
        for (int q = 0; q < 4; q++) {
            __nv_bfloat16 h = __float2bfloat16(vv[q]);
            hi4.h[q] = h;
            lo4.h[q] = __float2bfloat16(vv[q] - __bfloat162float(h));
        }
        __nv_bfloat16* dst;
        int k;
        if (k4 < 1024) { dst = g_Wx; k = k4; }
        else           { dst = g_Wh; k = k4 - 1024; }
        *(uint2*)(dst + (size_t)r * KP + k)        = hi4.u;
        *(uint2*)(dst + (size_t)r * KP + 1024 + k) = hi4.u;
        *(uint2*)(dst + (size_t)r * KP + 2048 + k) = lo4.u;
    }
    for (int i = idx; i < NG; i += stride) {
        int j = i >> 2, g = i & 3;
        const float* b = (g == 0) ? bf : (g == 1) ? bi : (g == 2) ? bg : bo;
        g_bias[i] = b[j];
    }
    for (int i = idx; i < BATCH * DH; i += stride) g_c[i] = 0.0f;
    for (int i = idx; i < BATCH * KP; i += stride) {
        g_hs[0][i] = __float2bfloat16(0.0f);
        g_hs[1][i] = __float2bfloat16(0.0f);
    }
}

// ---------------- X -> split bf16 ----------------
__global__ void xsplit_kernel(const float* __restrict__ X) {
    int idx = blockIdx.x * blockDim.x + threadIdx.x;
    int stride = gridDim.x * blockDim.x;
    for (int i = idx; i < MTOT * 256; i += stride) {
        int m = i >> 8;
        int k4 = (i & 255) * 4;
        float4 v = *(const float4*)(X + (size_t)m * DIN + k4);
        float vv[4] = {v.x, v.y, v.z, v.w};
        union { __nv_bfloat16 h[4]; uint2 u; } hi4, lo4;
#pragma unroll
        for (int q = 0; q < 4; q++) {
            __nv_bfloat16 h = __float2bfloat16(vv[q]);
            hi4.h[q] = h;
            lo4.h[q] = __float2bfloat16(vv[q] - __bfloat162float(h));
        }
        __nv_bfloat16* row = g_Xs + (size_t)m * KP;
        *(uint2*)(row + k4)        = hi4.u;
        *(uint2*)(row + 1024 + k4) = lo4.u;
        *(uint2*)(row + 2048 + k4) = hi4.u;
    }
}

// ============================================================
// xproj: pre[t][r][b] = Wx' . x'^T + bias
// CTA tile: 128 gate rows x 128 tokens.  8 warps, each m32 x n64.
// K chunks of 64, 3-stage cp.async pipeline. Smem rows padded to 72 bf16.
// ============================================================
#define XP_STAGE 18432                      // bf16 elems per stage (A 9216 + B 9216)
#define XP_SMEM  (3 * XP_STAGE * 2)         // 110592 bytes

__global__ __launch_bounds__(256, 1) void xproj_kernel() {
    extern __shared__ __nv_bfloat16 smem[];
    const uint32_t sb = smem_u32(smem);
    const int tid  = threadIdx.x;
    const int lane = tid & 31;
    const int wid  = tid >> 5;
    const int wm   = wid & 3;            // m block (32 rows)
    const int wn   = wid >> 2;           // n block (64 cols)
    const int r0   = blockIdx.x * 128;
    const int tok0 = blockIdx.y * 128;

    // loader mapping: 4 A-rows + 4 B-rows per thread per chunk
    const int lrow = tid >> 3;           // with +256 stride covers 0..127 (step 32)
    const int lseg = (tid & 7) * 8;

    // ldmatrix base addresses (byte offsets added per stage/k)
    const uint32_t aBase = sb + ((wm * 32 + (lane & 15)) * 72 + ((lane >> 4) * 8)) * 2;
    const uint32_t bBase = sb + (9216 + (wn * 64 + (lane & 15)) * 72 + ((lane >> 4) * 8)) * 2;

    float acc[2][8][4];
#pragma unroll
    for (int i = 0; i < 2; i++)
#pragma unroll
        for (int n = 0; n < 8; n++)
#pragma unroll
            for (int q = 0; q < 4; q++) acc[i][n][q] = 0.0f;

    const int NC = 48;

    // prologue: stages 0,1
#pragma unroll
    for (int s = 0; s < 2; s++) {
        const int kb = s * 64;
#pragma unroll
        for (int j = 0; j < 4; j++) {
            int row = lrow + j * 32;
            uint32_t da = sb + (s * XP_STAGE + row * 72 + lseg) * 2;
            CP16(da, g_Wx + (size_t)(r0 + row) * KP + kb + lseg);
            uint32_t db = sb + (s * XP_STAGE + 9216 + row * 72 + lseg) * 2;
            CP16(db, g_Xs + (size_t)(tok0 + row) * KP + kb + lseg);
        }
        CP_COMMIT();
    }

    for (int c = 0; c < NC; c++) {
        CP_WAIT(1);
        __syncthreads();
        if (c + 2 < NC) {
            const int s = (c + 2) % 3;
            const int kb = (c + 2) * 64;
#pragma unroll
            for (int j = 0; j < 4; j++) {
                int row = lrow + j * 32;
                uint32_t da = sb + (s * XP_STAGE + row * 72 + lseg) * 2;
                CP16(da, g_Wx + (size_t)(r0 + row) * KP + kb + lseg);
                uint32_t db = sb + (s * XP_STAGE + 9216 + row * 72 + lseg) * 2;
                CP16(db, g_Xs + (size_t)(tok0 + row) * KP + kb + lseg);
            }
        }
        CP_COMMIT();

        const uint32_t stOff = (uint32_t)((c % 3) * XP_STAGE) * 2;
#pragma unroll
        for (int s4 = 0; s4 < 4; s4++) {
            const uint32_t kOff = s4 * 32;   // 16 bf16 = 32 bytes
            uint32_t a0, a1, a2, a3, a4, a5, a6, a7;
            LDSM4(a0, a1, a2, a3, aBase + stOff + kOff);
            LDSM4(a4, a5, a6, a7, aBase + stOff + kOff + 16 * 144);
#pragma unroll
            for (int g = 0; g < 4; g++) {
                uint32_t b0, b1, b2, b3;
                LDSM4(b0, b1, b2, b3, bBase + stOff + kOff + g * 16 * 144);
                MMA(acc[0][2 * g],     a0, a1, a2, a3, b0, b2);
                MMA(acc[0][2 * g + 1], a0, a1, a2, a3, b1, b3);
                MMA(acc[1][2 * g],     a4, a5, a6, a7, b0, b2);
                MMA(acc[1][2 * g + 1], a4, a5, a6, a7, b1, b3);
            }
        }
    }
    CP_WAIT(0);

    // epilogue: bias + store float2 pairs to g_pre[t][r][b]
    const int gq = lane >> 2;
    const int t4 = lane & 3;
#pragma unroll
    for (int mi = 0; mi < 2; mi++) {
        const int R = r0 + wm * 32 + mi * 16 + gq;
        const float bias0 = g_bias[R];
        const float bias8 = g_bias[R + 8];
#pragma unroll
        for (int nb = 0; nb < 8; nb++) {
            const int n = wn * 64 + nb * 8 + t4 * 2;
            const int token = tok0 + n;
            const int tt = token >> 6;
            const int bb = token & 63;
            float* p0 = g_pre + ((size_t)tt * NG + R) * 64 + bb;
            float2 v0 = make_float2(acc[mi][nb][0] + bias0, acc[mi][nb][1] + bias0);
            *(float2*)p0 = v0;
            float2 v1 = make_float2(acc[mi][nb][2] + bias8, acc[mi][nb][3] + bias8);
            *(float2*)(p0 + 8 * 64) = v1;
        }
    }
}

// ============================================================
// step: z[r][b] = Wh' . h'^T ;  then gates + c/h update.
// 64 CTAs x 128 threads. CTA tile: 64 gate rows x 64 batch.
// 4 warps, each m16 x n64.  K chunks of 64, 4-stage cp.async.
// ============================================================
#define ST_STAGE 9216                        // bf16 elems per stage (A 4608 + B 4608)
#define ST_SMEM  (4 * ST_STAGE * 2)          // 73728 bytes

__global__ __launch_bounds__(128, 1) void step_kernel(float* __restrict__ out_h, int t) {
    extern __shared__ __nv_bfloat16 smem[];
    const uint32_t sb = smem_u32(smem);
    const int tid  = threadIdx.x;
    const int lane = tid & 31;
    const int wid  = tid >> 5;              // 0..3  -> m block of 16 rows
    const int r0   = blockIdx.x * 64;
    const __nv_bfloat16* hsrc = g_hs[t & 1];
    __nv_bfloat16* hdst = g_hs[(t + 1) & 1];
    const float* pre_t = g_pre + (size_t)t * NG * 64;

    const int lrow = tid >> 3;              // 0..15, +16 per j
    const int lseg = (tid & 7) * 8;

    const uint32_t aBase = sb + ((wid * 16 + (lane & 15)) * 72 + ((lane >> 4) * 8)) * 2;
    const uint32_t bBase = sb + (4608 + (lane & 15) * 72 + ((lane >> 4) * 8)) * 2;

    float acc[8][4];
#pragma unroll
    for (int n = 0; n < 8; n++)
#pragma unroll
        for (int q = 0; q < 4; q++) acc[n][q] = 0.0f;

    const int NC = 48;

#pragma unroll
    for (int s = 0; s < 3; s++) {
        const int kb = s * 64;
#pragma unroll
        for (int j = 0; j < 4; j++) {
            int row = lrow + j * 16;
            uint32_t da = sb + (s * ST_STAGE + row * 72 + lseg) * 2;
            CP16(da, g_Wh + (size_t)(r0 + row) * KP + kb + lseg);
            uint32_t db = sb + (s * ST_STAGE + 4608 + row * 72 + lseg) * 2;
            CP16(db, hsrc + (size_t)row * KP + kb + lseg);
        }
        CP_COMMIT();
    }

    for (int c = 0; c < NC; c++) {
        CP_WAIT(2);
        __syncthreads();
        if (c + 3 < NC) {
            const int s = (c + 3) & 3;
            const int kb = (c + 3) * 64;
#pragma unroll
            for (int j = 0; j < 4; j++) {
                int row = lrow + j * 16;
                uint32_t da = sb + (s * ST_STAGE + row * 72 + lseg) * 2;
                CP16(da, g_Wh + (size_t)(r0 + row) * KP + kb + lseg);
                uint32_t db = sb + (s * ST_STAGE + 4608 + row * 72 + lseg) * 2;
                CP16(db, hsrc + (size_t)row * KP + kb + lseg);
            }
        }
        CP_COMMIT();

        const uint32_t stOff = (uint32_t)((c & 3) * ST_STAGE) * 2;
#pragma unroll
        for (int s4 = 0; s4 < 4; s4++) {
            const uint32_t kOff = s4 * 32;
            uint32_t a0, a1, a2, a3;
            LDSM4(a0, a1, a2, a3, aBase + stOff + kOff);
#pragma unroll
            for (int g = 0; g < 4; g++) {
                uint32_t b0, b1, b2, b3;
                LDSM4(b0, b1, b2, b3, bBase + stOff + kOff + g * 16 * 144);
                MMA(acc[2 * g],     a0, a1, a2, a3, b0, b2);
                MMA(acc[2 * g + 1], a0, a1, a2, a3, b1, b3);
            }
        }
    }
    CP_WAIT(0);
    __syncthreads();

    // z = D + pre -> zbuf (aliases pipeline smem), stride 66 floats
    float* zbuf = (float*)smem;
    {
        const int gq = lane >> 2;
        const int t4 = lane & 3;
        const int row = wid * 16 + gq;
#pragma unroll
        for (int nb = 0; nb < 8; nb++) {
            const int col = nb * 8 + t4 * 2;
            float2 p0 = *(const float2*)(pre_t + (size_t)(r0 + row) * 64 + col);
            zbuf[row * 66 + col]     = acc[nb][0] + p0.x;
            zbuf[row * 66 + col + 1] = acc[nb][1] + p0.y;
            float2 p1 = *(const float2*)(pre_t + (size_t)(r0 + row + 8) * 64 + col);
            zbuf[(row + 8) * 66 + col]     = acc[nb][2] + p1.x;
            zbuf[(row + 8) * 66 + col + 1] = acc[nb][3] + p1.y;
        }
    }
    __syncthreads();

    // gate pass: jl-fast mapping -> coalesced stores in j
    const int jl = tid & 15;
    const int j  = (r0 >> 2) + jl;
    const int b0t = tid >> 4;            // 0..7
#pragma unroll
    for (int i = 0; i < 8; i++) {
        const int b = b0t + i * 8;
        float zf = zbuf[(jl * 4 + 0) * 66 + b];
        float zi = zbuf[(jl * 4 + 1) * 66 + b];
        float zg = zbuf[(jl * 4 + 2) * 66 + b];
        float zo = zbuf[(jl * 4 + 3) * 66 + b];
        float f  = sigf(zf);
        float ig = sigf(zi);
        float gg = tanhfast(zg);
        float oo = sigf(zo);
        float cn = f * g_c[b * DH + j] + ig * gg;
        g_c[b * DH + j] = cn;
        float h = oo * tanhfast(cn);
        out_h[(size_t)b * DH + j] = h;
        __nv_bfloat16 hh = __float2bfloat16(h);
        __nv_bfloat16 hl = __float2bfloat16(h - __bfloat162float(hh));
        hdst[(size_t)b * KP + j]        = hh;
        hdst[(size_t)b * KP + 1024 + j] = hl;
        hdst[(size_t)b * KP + 2048 + j] = hh;
    }
}

// ---------------- final: append h_n, c_n ----------------
__global__ void final_kernel(float* __restrict__ out) {
    int i = blockIdx.x * blockDim.x + threadIdx.x;
    if (i < BATCH * DH) {
        const size_t outs = (size_t)SEQ * BATCH * DH;
        out[outs + i] = out[(size_t)(SEQ - 1) * BATCH * DH + i];
        out[outs + BATCH * DH + i] = g_c[i];
    }
}

// ---------------- launch ----------------
extern "C" void kernel_launch(void* const* d_in, const int* in_sizes, int n_in,
                              void* d_out, int out_size) {
    const float* X  = (const float*)d_in[0];
    const float* Wf = (const float*)d_in[1];
    const float* bf = (const float*)d_in[2];
    const float* Wi = (const float*)d_in[3];
    const float* bi = (const float*)d_in[4];
    const float* Wg = (const float*)d_in[5];
    const float* bg = (const float*)d_in[6];
    const float* Wo = (const float*)d_in[7];
    const float* bo = (const float*)d_in[8];
    float* out = (float*)d_out;

    static int attr_done = 0;
    if (!attr_done) {
        cudaFuncSetAttribute(xproj_kernel, cudaFuncAttributeMaxDynamicSharedMemorySize, XP_SMEM);
        cudaFuncSetAttribute(step_kernel,  cudaFuncAttributeMaxDynamicSharedMemorySize, ST_SMEM);
        attr_done = 1;
    }

    prep_kernel<<<2048, 256>>>(Wf, bf, Wi, bi, Wg, bg, Wo, bo);
    xsplit_kernel<<<4096, 256>>>(X);

    dim3 gx(32, 256);                        // x fastest: gate tiles share token tile in L2
    xproj_kernel<<<gx, 256, XP_SMEM>>>();

    for (int t = 0; t < SEQ; t++)
        step_kernel<<<64, 128, ST_SMEM>>>(out + (size_t)t * BATCH * DH, t);

    final_kernel<<<(BATCH * DH + 255) / 256, 256>>>(out);
}

// round 6
// speedup vs baseline: 3.8379x; 1.9842x over previous
#include <cuda_runtime.h>
#include <cuda_bf16.h>
#include <stdint.h>

// ---------------- problem constants ----------------
#define SEQ   512
#define BATCH 64
#define DIN   1024
#define DH    1024
#define NG    4096            // 4 gates * DH, reordered r = j*4 + g
#define KP    3072            // xproj split-K: A=[hi|hi|lo], B=[hi|lo|hi]
#define K2    2048            // recurrence: A=[hi|lo], B=[hi|lo], 3 mma passes
#define MTOT  (SEQ * BATCH)

// ---------------- device scratch ----------------
__device__ __align__(16) __nv_bfloat16 g_Wx[(size_t)NG * KP];     // 25 MB
__device__ __align__(16) __nv_bfloat16 g_Wh2[(size_t)NG * K2];    // 16.8 MB [hi|lo]
__device__ __align__(16) __nv_bfloat16 g_Xs[(size_t)MTOT * KP];   // 192 MB
__device__ __align__(16) __nv_bfloat16 g_hs[2][BATCH * K2];       // h split ping-pong
__device__ float g_bias[NG];
__device__ float g_pre[(size_t)SEQ * NG * BATCH];                 // 512 MB pre[t][r][b]
__device__ int   g_sync;                                          // step barrier

// ---------------- asm helpers (baseline PTX only) ----------------
__device__ __forceinline__ uint32_t smem_u32(const void* p) {
    uint32_t a;
    asm("{ .reg .u64 t; cvta.to.shared.u64 t, %1; cvt.u32.u64 %0, t; }" : "=r"(a) : "l"(p));
    return a;
}
#define CP16(dst, src) asm volatile("cp.async.cg.shared.global [%0], [%1], 16;" :: "r"(dst), "l"(src))
#define CP_COMMIT()    asm volatile("cp.async.commit_group;" ::: "memory")
#define CP_WAIT(n)     asm volatile("cp.async.wait_group %0;" :: "n"(n) : "memory")

#define LDSM4(r0, r1, r2, r3, a) \
    asm volatile("ldmatrix.sync.aligned.m8n8.x4.shared.b16 {%0,%1,%2,%3}, [%4];" \
                 : "=r"(r0), "=r"(r1), "=r"(r2), "=r"(r3) : "r"(a))

#define MMA(d, a0, a1, a2, a3, b0, b1) \
    asm volatile("mma.sync.aligned.m16n8k16.row.col.f32.bf16.bf16.f32 " \
                 "{%0,%1,%2,%3}, {%4,%5,%6,%7}, {%8,%9}, {%0,%1,%2,%3};" \
                 : "+f"((d)[0]), "+f"((d)[1]), "+f"((d)[2]), "+f"((d)[3]) \
                 : "r"(a0), "r"(a1), "r"(a2), "r"(a3), "r"(b0), "r"(b1))

__device__ __forceinline__ float sigf(float x) { return 1.0f / (1.0f + __expf(-x)); }
__device__ __forceinline__ float tanhfast(float x) { return 1.0f - 2.0f / (__expf(2.0f * x) + 1.0f); }

// ---------------- prep: split weights/bias, zero states ----------------
__global__ void prep_kernel(const float* __restrict__ Wf, const float* __restrict__ bf,
                            const float* __restrict__ Wi, const float* __restrict__ bi,
                            const float* __restrict__ Wg, const float* __restrict__ bg,
                            const float* __restrict__ Wo, const float* __restrict__ bo) {
    int idx = blockIdx.x * blockDim.x + threadIdx.x;
    int stride = gridDim.x * blockDim.x;
    if (idx == 0) g_sync = 0;
    for (int i = idx; i < NG * 512; i += stride) {
        int r = i >> 9;
        int k4 = (i & 511) * 4;
        int j = r >> 2, g = r & 3;
        const float* W = (g == 0) ? Wf : (g == 1) ? Wi : (g == 2) ? Wg : Wo;
        float4 v = *(const float4*)(W + (size_t)j * 2048 + k4);
        float vv[4] = {v.x, v.y, v.z, v.w};
        union { __nv_bfloat16 h[4]; uint2 u; } hi4, lo4;
#pragma unroll
        for (int q = 0; q < 4; q++) {
            __nv_bfloat16 h = __float2bfloat16(vv[q]);
            hi4.h[q] = h;
            lo4.h[q] = __float2bfloat16(vv[q] - __bfloat162float(h));
        }
        if (k4 < 1024) {     // x-part -> g_Wx  [hi|hi|lo] over KP
            *(uint2*)(g_Wx + (size_t)r * KP + k4)        = hi4.u;
            *(uint2*)(g_Wx + (size_t)r * KP + 1024 + k4) = hi4.u;
            *(uint2*)(g_Wx + (size_t)r * KP + 2048 + k4) = lo4.u;
        } else {             // h-part -> g_Wh2 [hi|lo] over K2
            int k = k4 - 1024;
            *(uint2*)(g_Wh2 + (size_t)r * K2 + k)        = hi4.u;
            *(uint2*)(g_Wh2 + (size_t)r * K2 + 1024 + k) = lo4.u;
        }
    }
    for (int i = idx; i < NG; i += stride) {
        int j = i >> 2, g = i & 3;
        const float* b = (g == 0) ? bf : (g == 1) ? bi : (g == 2) ? bg : bo;
        g_bias[i] = b[j];
    }
    for (int i = idx; i < BATCH * K2; i += stride) {
        g_hs[0][i] = __float2bfloat16(0.0f);
        g_hs[1][i] = __float2bfloat16(0.0f);
    }
}

// ---------------- X -> split bf16 ----------------
__global__ void xsplit_kernel(const float* __restrict__ X) {
    int idx = blockIdx.x * blockDim.x + threadIdx.x;
    int stride = gridDim.x * blockDim.x;
    for (int i = idx; i < MTOT * 256; i += stride) {
        int m = i >> 8;
        int k4 = (i & 255) * 4;
        float4 v = *(const float4*)(X + (size_t)m * DIN + k4);
        float vv[4] = {v.x, v.y, v.z, v.w};
        union { __nv_bfloat16 h[4]; uint2 u; } hi4, lo4;
#pragma unroll
        for (int q = 0; q < 4; q++) {
            __nv_bfloat16 h = __float2bfloat16(vv[q]);
            hi4.h[q] = h;
            lo4.h[q] = __float2bfloat16(vv[q] - __bfloat162float(h));
        }
        __nv_bfloat16* row = g_Xs + (size_t)m * KP;
        *(uint2*)(row + k4)        = hi4.u;
        *(uint2*)(row + 1024 + k4) = lo4.u;
        *(uint2*)(row + 2048 + k4) = hi4.u;
    }
}

// ============================================================
// xproj (unchanged, verified in R4): pre[t][r][b] = Wx' . x'^T + bias
// ============================================================
#define XP_STAGE 18432
#define XP_SMEM  (3 * XP_STAGE * 2)

__global__ __launch_bounds__(256, 1) void xproj_kernel() {
    extern __shared__ __nv_bfloat16 smem[];
    const uint32_t sb = smem_u32(smem);
    const int tid  = threadIdx.x;
    const int lane = tid & 31;
    const int wid  = tid >> 5;
    const int wm   = wid & 3;
    const int wn   = wid >> 2;
    const int r0   = blockIdx.x * 128;
    const int tok0 = blockIdx.y * 128;

    const int lrow = tid >> 3;
    const int lseg = (tid & 7) * 8;

    const uint32_t aBase = sb + ((wm * 32 + (lane & 15)) * 72 + ((lane >> 4) * 8)) * 2;
    const uint32_t bBase = sb + (9216 + (wn * 64 + (lane & 15)) * 72 + ((lane >> 4) * 8)) * 2;

    float acc[2][8][4];
#pragma unroll
    for (int i = 0; i < 2; i++)
#pragma unroll
        for (int n = 0; n < 8; n++)
#pragma unroll
            for (int q = 0; q < 4; q++) acc[i][n][q] = 0.0f;

    const int NC = 48;
#pragma unroll
    for (int s = 0; s < 2; s++) {
        const int kb = s * 64;
#pragma unroll
        for (int j = 0; j < 4; j++) {
            int row = lrow + j * 32;
            CP16(sb + (s * XP_STAGE + row * 72 + lseg) * 2,
                 g_Wx + (size_t)(r0 + row) * KP + kb + lseg);
            CP16(sb + (s * XP_STAGE + 9216 + row * 72 + lseg) * 2,
                 g_Xs + (size_t)(tok0 + row) * KP + kb + lseg);
        }
        CP_COMMIT();
    }

    for (int c = 0; c < NC; c++) {
        CP_WAIT(1);
        __syncthreads();
        if (c + 2 < NC) {
            const int s = (c + 2) % 3;
            const int kb = (c + 2) * 64;
#pragma unroll
            for (int j = 0; j < 4; j++) {
                int row = lrow + j * 32;
                CP16(sb + (s * XP_STAGE + row * 72 + lseg) * 2,
                     g_Wx + (size_t)(r0 + row) * KP + kb + lseg);
                CP16(sb + (s * XP_STAGE + 9216 + row * 72 + lseg) * 2,
                     g_Xs + (size_t)(tok0 + row) * KP + kb + lseg);
            }
        }
        CP_COMMIT();

        const uint32_t stOff = (uint32_t)((c % 3) * XP_STAGE) * 2;
#pragma unroll
        for (int s4 = 0; s4 < 4; s4++) {
            const uint32_t kOff = s4 * 32;
            uint32_t a0, a1, a2, a3, a4, a5, a6, a7;
            LDSM4(a0, a1, a2, a3, aBase + stOff + kOff);
            LDSM4(a4, a5, a6, a7, aBase + stOff + kOff + 16 * 144);
#pragma unroll
            for (int g = 0; g < 4; g++) {
                uint32_t b0, b1, b2, b3;
                LDSM4(b0, b1, b2, b3, bBase + stOff + kOff + g * 16 * 144);
                MMA(acc[0][2 * g],     a0, a1, a2, a3, b0, b2);
                MMA(acc[0][2 * g + 1], a0, a1, a2, a3, b1, b3);
                MMA(acc[1][2 * g],     a4, a5, a6, a7, b0, b2);
                MMA(acc[1][2 * g + 1], a4, a5, a6, a7, b1, b3);
            }
        }
    }
    CP_WAIT(0);

    const int gq = lane >> 2;
    const int t4 = lane & 3;
#pragma unroll
    for (int mi = 0; mi < 2; mi++) {
        const int R = r0 + wm * 32 + mi * 16 + gq;
        const float bias0 = g_bias[R];
        const float bias8 = g_bias[R + 8];
#pragma unroll
        for (int nb = 0; nb < 8; nb++) {
            const int n = wn * 64 + nb * 8 + t4 * 2;
            const int token = tok0 + n;
            const int tt = token >> 6;
            const int bb = token & 63;
            float* p0 = g_pre + ((size_t)tt * NG + R) * 64 + bb;
            *(float2*)p0 = make_float2(acc[mi][nb][0] + bias0, acc[mi][nb][1] + bias0);
            *(float2*)(p0 + 8 * 64) = make_float2(acc[mi][nb][2] + bias8, acc[mi][nb][3] + bias8);
        }
    }
}

// ============================================================
// persistent recurrence: 128 CTAs x 256 thr, all 512 steps.
// CTA tile: M=32 gate rows, N=64 batch. A panel (32x2048) resident in smem.
// Per chunk (k=64): B_hi + B_lo staged; 3 mma passes (Ahi*Bhi, Alo*Bhi, Ahi*Blo).
// ============================================================
#define SA_BYTES   131584                   // 32 rows * 2056 * 2
#define SB_STAGE   18432                    // (64*72)*2 * 2 (hi+lo)
#define SB_OFFSET  SA_BYTES
#define ZB_OFFSET  (SA_BYTES + 3 * SB_STAGE)          // 186880
#define PS_SMEM    (ZB_OFFSET + 32 * 66 * 4)          // 195328

__global__ __launch_bounds__(256, 1) void persistent_kernel(float* __restrict__ out) {
    extern __shared__ __nv_bfloat16 smem[];
    const uint32_t sb = smem_u32(smem);
    const int tid  = threadIdx.x;
    const int lane = tid & 31;
    const int wid  = tid >> 5;
    const int wm   = wid & 1;               // m block of 16
    const int wn   = wid >> 1;              // n block of 16
    const int r0   = blockIdx.x * 32;

    // ---- load A panel once: 32 rows x 2048 bf16 (256 uint4/row), smem stride 2056 ----
    for (int i = tid; i < 32 * 256; i += 256) {
        int row = i >> 8;
        int seg = (i & 255) * 8;
        uint4 v = *(const uint4*)(g_Wh2 + (size_t)(r0 + row) * K2 + seg);
        *(uint4*)((char*)smem + (row * 2056 + seg) * 2) = v;
    }
    __syncthreads();

    // ldmatrix bases
    const uint32_t aBase = sb + ((wm * 16 + (lane & 15)) * 2056 + (lane >> 4) * 8) * 2;
    const uint32_t bBase = sb + SB_OFFSET + ((wn * 16 + (lane & 15)) * 72 + (lane >> 4) * 8) * 2;
    float* zbuf = (float*)((char*)smem + ZB_OFFSET);

    // cell registers: thread owns cells (b = tid>>2, jl = (tid&3)*2 + {0,1})
    const int cb  = tid >> 2;
    const int jp  = tid & 3;
    float creg0 = 0.0f, creg1 = 0.0f;

    for (int t = 0; t < SEQ; t++) {
        const __nv_bfloat16* hsrc = g_hs[t & 1];
        __nv_bfloat16* hdst = g_hs[(t + 1) & 1];
        const float* pre_t = g_pre + (size_t)t * NG * 64;

        float acc[2][4];
#pragma unroll
        for (int n = 0; n < 2; n++)
#pragma unroll
            for (int q = 0; q < 4; q++) acc[n][q] = 0.0f;

        // prologue: chunks 0,1
#pragma unroll
        for (int s = 0; s < 2; s++) {
#pragma unroll
            for (int i = 0; i < 4; i++) {
                int idx = tid + i * 256;
                int hl = idx >> 9, row = (idx >> 3) & 63, sg = idx & 7;
                CP16(sb + SB_OFFSET + s * SB_STAGE + hl * 9216 + (row * 72 + sg * 8) * 2,
                     hsrc + (size_t)row * K2 + hl * 1024 + s * 64 + sg * 8);
            }
            CP_COMMIT();
        }

        for (int kc = 0; kc < 16; kc++) {
            CP_WAIT(1);
            __syncthreads();
            if (kc + 2 < 16) {
                const int s = (kc + 2) % 3;
#pragma unroll
                for (int i = 0; i < 4; i++) {
                    int idx = tid + i * 256;
                    int hl = idx >> 9, row = (idx >> 3) & 63, sg = idx & 7;
                    CP16(sb + SB_OFFSET + s * SB_STAGE + hl * 9216 + (row * 72 + sg * 8) * 2,
                         hsrc + (size_t)row * K2 + hl * 1024 + (kc + 2) * 64 + sg * 8);
                }
            }
            CP_COMMIT();

            const uint32_t stB = (uint32_t)((kc % 3) * SB_STAGE);
            const uint32_t kA  = (uint32_t)(kc * 64) * 2;
#pragma unroll
            for (int s4 = 0; s4 < 4; s4++) {
                uint32_t ah0, ah1, ah2, ah3, al0, al1, al2, al3;
                LDSM4(ah0, ah1, ah2, ah3, aBase + kA + s4 * 32);
                LDSM4(al0, al1, al2, al3, aBase + kA + s4 * 32 + 2048);   // +1024 elems (lo)
                uint32_t bh0, bh1, bh2, bh3, blo0, blo1, blo2, blo3;
                LDSM4(bh0, bh1, bh2, bh3, bBase + stB + s4 * 32);
                LDSM4(blo0, blo1, blo2, blo3, bBase + stB + s4 * 32 + 9216);
                MMA(acc[0], ah0, ah1, ah2, ah3, bh0, bh2);
                MMA(acc[1], ah0, ah1, ah2, ah3, bh1, bh3);
                MMA(acc[0], al0, al1, al2, al3, bh0, bh2);
                MMA(acc[1], al0, al1, al2, al3, bh1, bh3);
                MMA(acc[0], ah0, ah1, ah2, ah3, blo0, blo2);
                MMA(acc[1], ah0, ah1, ah2, ah3, blo1, blo3);
            }
        }

        // ---- z = acc + pre -> zbuf ----
        {
            const int gq = lane >> 2;
            const int t4 = lane & 3;
            const int R1 = wm * 16 + gq;
#pragma unroll
            for (int nb = 0; nb < 2; nb++) {
                const int col = wn * 16 + nb * 8 + t4 * 2;
                float2 p0 = *(const float2*)(pre_t + (size_t)(r0 + R1) * 64 + col);
                zbuf[R1 * 66 + col]     = acc[nb][0] + p0.x;
                zbuf[R1 * 66 + col + 1] = acc[nb][1] + p0.y;
                float2 p1 = *(const float2*)(pre_t + (size_t)(r0 + R1 + 8) * 64 + col);
                zbuf[(R1 + 8) * 66 + col]     = acc[nb][2] + p1.x;
                zbuf[(R1 + 8) * 66 + col + 1] = acc[nb][3] + p1.y;
            }
        }
        __syncthreads();

        // ---- gate pass: 2 cells per thread, c in registers ----
        float* out_t = out + (size_t)t * BATCH * DH;
#pragma unroll
        for (int q = 0; q < 2; q++) {
            const int jl = jp * 2 + q;
            const int j  = (r0 >> 2) + jl;
            float zf = zbuf[(jl * 4 + 0) * 66 + cb];
            float zi = zbuf[(jl * 4 + 1) * 66 + cb];
            float zg = zbuf[(jl * 4 + 2) * 66 + cb];
            float zo = zbuf[(jl * 4 + 3) * 66 + cb];
            float f  = sigf(zf);
            float ig = sigf(zi);
            float gg = tanhfast(zg);
            float oo = sigf(zo);
            float cprev = q ? creg1 : creg0;
            float cn = f * cprev + ig * gg;
            if (q) creg1 = cn; else creg0 = cn;
            float h = oo * tanhfast(cn);
            out_t[(size_t)cb * DH + j] = h;
            __nv_bfloat16 hh = __float2bfloat16(h);
            __nv_bfloat16 hl = __float2bfloat16(h - __bfloat162float(hh));
            hdst[(size_t)cb * K2 + j]        = hh;
            hdst[(size_t)cb * K2 + 1024 + j] = hl;
            if (t == SEQ - 1) {
                const size_t outs = (size_t)SEQ * BATCH * DH;
                out[outs + (size_t)cb * DH + j] = h;               // h_n
                out[outs + BATCH * DH + (size_t)cb * DH + j] = cn; // c_n
            }
        }

        // ---- global step barrier ----
        __threadfence();
        __syncthreads();
        if (tid == 0) {
            atomicAdd(&g_sync, 1);
            const int target = 128 * (t + 1);
            while (*(volatile int*)&g_sync < target) {}
            __threadfence();
        }
        __syncthreads();
    }
}

// ---------------- launch ----------------
extern "C" void kernel_launch(void* const* d_in, const int* in_sizes, int n_in,
                              void* d_out, int out_size) {
    const float* X  = (const float*)d_in[0];
    const float* Wf = (const float*)d_in[1];
    const float* bf = (const float*)d_in[2];
    const float* Wi = (const float*)d_in[3];
    const float* bi = (const float*)d_in[4];
    const float* Wg = (const float*)d_in[5];
    const float* bg = (const float*)d_in[6];
    const float* Wo = (const float*)d_in[7];
    const float* bo = (const float*)d_in[8];
    float* out = (float*)d_out;

    static int attr_done = 0;
    if (!attr_done) {
        cudaFuncSetAttribute(xproj_kernel, cudaFuncAttributeMaxDynamicSharedMemorySize, XP_SMEM);
        cudaFuncSetAttribute(persistent_kernel, cudaFuncAttributeMaxDynamicSharedMemorySize, PS_SMEM);
        attr_done = 1;
    }

    prep_kernel<<<2048, 256>>>(Wf, bf, Wi, bi, Wg, bg, Wo, bo);
    xsplit_kernel<<<4096, 256>>>(X);

    dim3 gx(32, 256);
    xproj_kernel<<<gx, 256, XP_SMEM>>>();

    persistent_kernel<<<128, 256, PS_SMEM>>>(out);
}

// round 7
// speedup vs baseline: 4.3245x; 1.1268x over previous
#include <cuda_runtime.h>
#include <cuda_fp16.h>
#include <stdint.h>

// ---------------- problem constants ----------------
#define SEQ   512
#define BATCH 64
#define DIN   1024
#define DH    1024
#define NG    4096            // 4 gates * DH, reordered r = j*4 + g
#define K2    2048            // B = [xh | xl] fp16 (exact split); A = W fp16, 1024 wide, mod-1024
#define MTOT  (SEQ * BATCH)

// ---------------- device scratch ----------------
__device__ __align__(16) __half g_Wxf[(size_t)NG * 1024];    // 8.4 MB fp16
__device__ __align__(16) __half g_Whf[(size_t)NG * 1024];    // 8.4 MB fp16
__device__ __align__(16) __half g_Xs2[(size_t)MTOT * K2];    // 128 MB [xh|xl]
__device__ __align__(16) __half g_hs[2][BATCH * K2];         // h split ping-pong
__device__ float g_bias[NG];
__device__ float g_pre[(size_t)SEQ * NG * BATCH];            // 512 MB pre[t][r][b]
__device__ int   g_sync;                                     // step barrier

// ---------------- asm helpers (baseline PTX only) ----------------
__device__ __forceinline__ uint32_t smem_u32(const void* p) {
    uint32_t a;
    asm("{ .reg .u64 t; cvta.to.shared.u64 t, %1; cvt.u32.u64 %0, t; }" : "=r"(a) : "l"(p));
    return a;
}
#define CP16(dst, src) asm volatile("cp.async.cg.shared.global [%0], [%1], 16;" :: "r"(dst), "l"(src))
#define CP_COMMIT()    asm volatile("cp.async.commit_group;" ::: "memory")
#define CP_WAIT(n)     asm volatile("cp.async.wait_group %0;" :: "n"(n) : "memory")

#define LDSM4(r0, r1, r2, r3, a) \
    asm volatile("ldmatrix.sync.aligned.m8n8.x4.shared.b16 {%0,%1,%2,%3}, [%4];" \
                 : "=r"(r0), "=r"(r1), "=r"(r2), "=r"(r3) : "r"(a))

#define MMAH(d, a0, a1, a2, a3, b0, b1) \
    asm volatile("mma.sync.aligned.m16n8k16.row.col.f32.f16.f16.f32 " \
                 "{%0,%1,%2,%3}, {%4,%5,%6,%7}, {%8,%9}, {%0,%1,%2,%3};" \
                 : "+f"((d)[0]), "+f"((d)[1]), "+f"((d)[2]), "+f"((d)[3]) \
                 : "r"(a0), "r"(a1), "r"(a2), "r"(a3), "r"(b0), "r"(b1))

__device__ __forceinline__ float sigf(float x) { return 1.0f / (1.0f + __expf(-x)); }
__device__ __forceinline__ float tanhfast(float x) { return 1.0f - 2.0f / (__expf(2.0f * x) + 1.0f); }

// ---------------- prep: weights -> fp16, bias, zero states ----------------
__global__ void prep_kernel(const float* __restrict__ Wf, const float* __restrict__ bf,
                            const float* __restrict__ Wi, const float* __restrict__ bi,
                            const float* __restrict__ Wg, const float* __restrict__ bg,
                            const float* __restrict__ Wo, const float* __restrict__ bo) {
    int idx = blockIdx.x * blockDim.x + threadIdx.x;
    int stride = gridDim.x * blockDim.x;
    if (idx == 0) g_sync = 0;
    for (int i = idx; i < NG * 512; i += stride) {
        int r = i >> 9;
        int k4 = (i & 511) * 4;          // 0..2044 over the 2048-wide concat row
        int j = r >> 2, g = r & 3;
        const float* W = (g == 0) ? Wf : (g == 1) ? Wi : (g == 2) ? Wg : Wo;
        float4 v = *(const float4*)(W + (size_t)j * 2048 + k4);
        union { __half h[4]; uint2 u; } h4;
        h4.h[0] = __float2half(v.x); h4.h[1] = __float2half(v.y);
        h4.h[2] = __float2half(v.z); h4.h[3] = __float2half(v.w);
        if (k4 < 1024) *(uint2*)(g_Wxf + (size_t)r * 1024 + k4)          = h4.u;
        else           *(uint2*)(g_Whf + (size_t)r * 1024 + (k4 - 1024)) = h4.u;
    }
    for (int i = idx; i < NG; i += stride) {
        int j = i >> 2, g = i & 3;
        const float* b = (g == 0) ? bf : (g == 1) ? bi : (g == 2) ? bg : bo;
        g_bias[i] = b[j];
    }
    for (int i = idx; i < BATCH * K2; i += stride) {
        g_hs[0][i] = __float2half(0.0f);
        g_hs[1][i] = __float2half(0.0f);
    }
}

// ---------------- X -> exact fp16 split [xh | xl] ----------------
__global__ void xsplit_kernel(const float* __restrict__ X) {
    int idx = blockIdx.x * blockDim.x + threadIdx.x;
    int stride = gridDim.x * blockDim.x;
    for (int i = idx; i < MTOT * 256; i += stride) {
        int m = i >> 8;
        int k4 = (i & 255) * 4;
        float4 v = *(const float4*)(X + (size_t)m * DIN + k4);
        float vv[4] = {v.x, v.y, v.z, v.w};
        union { __half h[4]; uint2 u; } hi4, lo4;
#pragma unroll
        for (int q = 0; q < 4; q++) {
            __half h = __float2half(vv[q]);
            hi4.h[q] = h;
            lo4.h[q] = __float2half(vv[q] - __half2float(h));
        }
        __half* row = g_Xs2 + (size_t)m * K2;
        *(uint2*)(row + k4)        = hi4.u;
        *(uint2*)(row + 1024 + k4) = lo4.u;
    }
}

// ============================================================
// xproj: pre[t][r][b] = Wxf . [xh|xl]^T + bias
// CTA tile 128 gates x 128 tokens, 8 warps (m32 x n64), k=64 chunks,
// NC=32 over K2=2048; A (1024-wide) addressed mod 1024. 3-stage cp.async.
// ============================================================
#define XP_STAGE 18432                      // elems per stage (A 9216 + B 9216)
#define XP_SMEM  (3 * XP_STAGE * 2)

__global__ __launch_bounds__(256, 1) void xproj_kernel() {
    extern __shared__ __half smem[];
    const uint32_t sb = smem_u32(smem);
    const int tid  = threadIdx.x;
    const int lane = tid & 31;
    const int wid  = tid >> 5;
    const int wm   = wid & 3;
    const int wn   = wid >> 2;
    const int r0   = blockIdx.x * 128;
    const int tok0 = blockIdx.y * 128;

    const int lrow = tid >> 3;
    const int lseg = (tid & 7) * 8;

    const uint32_t aBase = sb + ((wm * 32 + (lane & 15)) * 72 + ((lane >> 4) * 8)) * 2;
    const uint32_t bBase = sb + (9216 + (wn * 64 + (lane & 15)) * 72 + ((lane >> 4) * 8)) * 2;

    float acc[2][8][4];
#pragma unroll
    for (int i = 0; i < 2; i++)
#pragma unroll
        for (int n = 0; n < 8; n++)
#pragma unroll
            for (int q = 0; q < 4; q++) acc[i][n][q] = 0.0f;

    const int NC = 32;
#pragma unroll
    for (int s = 0; s < 2; s++) {
        const int kb = s * 64;
#pragma unroll
        for (int j = 0; j < 4; j++) {
            int row = lrow + j * 32;
            CP16(sb + (s * XP_STAGE + row * 72 + lseg) * 2,
                 g_Wxf + (size_t)(r0 + row) * 1024 + (kb & 1023) + lseg);
            CP16(sb + (s * XP_STAGE + 9216 + row * 72 + lseg) * 2,
                 g_Xs2 + (size_t)(tok0 + row) * K2 + kb + lseg);
        }
        CP_COMMIT();
    }

    for (int c = 0; c < NC; c++) {
        CP_WAIT(1);
        __syncthreads();
        if (c + 2 < NC) {
            const int s = (c + 2) % 3;
            const int kb = (c + 2) * 64;
#pragma unroll
            for (int j = 0; j < 4; j++) {
                int row = lrow + j * 32;
                CP16(sb + (s * XP_STAGE + row * 72 + lseg) * 2,
                     g_Wxf + (size_t)(r0 + row) * 1024 + (kb & 1023) + lseg);
                CP16(sb + (s * XP_STAGE + 9216 + row * 72 + lseg) * 2,
                     g_Xs2 + (size_t)(tok0 + row) * K2 + kb + lseg);
            }
        }
        CP_COMMIT();

        const uint32_t stOff = (uint32_t)((c % 3) * XP_STAGE) * 2;
#pragma unroll
        for (int s4 = 0; s4 < 4; s4++) {
            const uint32_t kOff = s4 * 32;
            uint32_t a0, a1, a2, a3, a4, a5, a6, a7;
            LDSM4(a0, a1, a2, a3, aBase + stOff + kOff);
            LDSM4(a4, a5, a6, a7, aBase + stOff + kOff + 16 * 144);
#pragma unroll
            for (int g = 0; g < 4; g++) {
                uint32_t b0, b1, b2, b3;
                LDSM4(b0, b1, b2, b3, bBase + stOff + kOff + g * 16 * 144);
                MMAH(acc[0][2 * g],     a0, a1, a2, a3, b0, b2);
                MMAH(acc[0][2 * g + 1], a0, a1, a2, a3, b1, b3);
                MMAH(acc[1][2 * g],     a4, a5, a6, a7, b0, b2);
                MMAH(acc[1][2 * g + 1], a4, a5, a6, a7, b1, b3);
            }
        }
    }
    CP_WAIT(0);

    const int gq = lane >> 2;
    const int t4 = lane & 3;
#pragma unroll
    for (int mi = 0; mi < 2; mi++) {
        const int R = r0 + wm * 32 + mi * 16 + gq;
        const float bias0 = g_bias[R];
        const float bias8 = g_bias[R + 8];
#pragma unroll
        for (int nb = 0; nb < 8; nb++) {
            const int n = wn * 64 + nb * 8 + t4 * 2;
            const int token = tok0 + n;
            const int tt = token >> 6;
            const int bb = token & 63;
            float* p0 = g_pre + ((size_t)tt * NG + R) * 64 + bb;
            *(float2*)p0 = make_float2(acc[mi][nb][0] + bias0, acc[mi][nb][1] + bias0);
            *(float2*)(p0 + 8 * 64) = make_float2(acc[mi][nb][2] + bias8, acc[mi][nb][3] + bias8);
        }
    }
}

// ============================================================
// persistent recurrence: 128 CTAs x 256 thr, all 512 steps.
// CTA: M=32 gate rows, N=64 batch. A = Whf panel (32x1024 fp16) resident.
// B = [hh|hl] (64x2048 fp16), k-chunks of 256, 3-stage cp.async, 8 iters.
// A addressed mod 1024 (chunks 4..7 reuse the panel).
// ============================================================
#define PS_A_STRIDE 1032
#define PS_A_BYTES  (32 * PS_A_STRIDE * 2)            // 66048
#define PS_B_STRIDE 264
#define PS_B_STAGE  (64 * PS_B_STRIDE * 2)            // 33792
#define PS_B_OFF    PS_A_BYTES
#define PS_ZB_OFF   (PS_A_BYTES + 3 * PS_B_STAGE)     // 167424
#define PS_SMEM     (PS_ZB_OFF + 32 * 66 * 4)         // 175872

__global__ __launch_bounds__(256, 1) void persistent_kernel(float* __restrict__ out) {
    extern __shared__ __half smem[];
    const uint32_t sb = smem_u32(smem);
    const int tid  = threadIdx.x;
    const int lane = tid & 31;
    const int wid  = tid >> 5;
    const int wm   = wid & 1;               // m block of 16
    const int wn   = wid >> 1;              // n block of 16
    const int r0   = blockIdx.x * 32;

    // ---- A panel resident: 32 rows x 1024 fp16 (128 uint4/row) ----
    for (int i = tid; i < 32 * 128; i += 256) {
        int row = i >> 7;
        int seg = (i & 127) * 8;
        uint4 v = *(const uint4*)(g_Whf + (size_t)(r0 + row) * 1024 + seg);
        *(uint4*)((char*)smem + (row * PS_A_STRIDE + seg) * 2) = v;
    }
    __syncthreads();

    const uint32_t aBase = sb + ((wm * 16 + (lane & 15)) * PS_A_STRIDE + (lane >> 4) * 8) * 2;
    const uint32_t bBase = sb + PS_B_OFF + ((wn * 16 + (lane & 15)) * PS_B_STRIDE + (lane >> 4) * 8) * 2;
    float* zbuf = (float*)((char*)smem + PS_ZB_OFF);

    // epilogue/gate thread mapping
    const int gq  = lane >> 2;
    const int t4  = lane & 3;
    const int R1  = wm * 16 + gq;
    const int col0 = wn * 16 + t4 * 2;
    const int col1 = wn * 16 + 8 + t4 * 2;
    const int cb  = tid >> 2;
    const int jp  = tid & 3;
    float creg0 = 0.0f, creg1 = 0.0f;

    for (int t = 0; t < SEQ; t++) {
        const __half* hsrc = g_hs[t & 1];
        __half* hdst = g_hs[(t + 1) & 1];
        const float* pre_t = g_pre + (size_t)t * NG * 64;

        // prefetch pre for this CTA's tile (consumed post-mainloop)
        float2 p00 = *(const float2*)(pre_t + (size_t)(r0 + R1) * 64 + col0);
        float2 p01 = *(const float2*)(pre_t + (size_t)(r0 + R1 + 8) * 64 + col0);
        float2 p10 = *(const float2*)(pre_t + (size_t)(r0 + R1) * 64 + col1);
        float2 p11 = *(const float2*)(pre_t + (size_t)(r0 + R1 + 8) * 64 + col1);

        float acc[2][4];
#pragma unroll
        for (int n = 0; n < 2; n++)
#pragma unroll
            for (int q = 0; q < 4; q++) acc[n][q] = 0.0f;

        // prologue: chunks 0,1 (8 cp16 per thread per chunk)
#pragma unroll
        for (int s = 0; s < 2; s++) {
#pragma unroll
            for (int i = 0; i < 8; i++) {
                int idx = tid + i * 256;
                int row = idx >> 5, seg = (idx & 31) * 8;
                CP16(sb + PS_B_OFF + s * PS_B_STAGE + (row * PS_B_STRIDE + seg) * 2,
                     hsrc + (size_t)row * K2 + s * 256 + seg);
            }
            CP_COMMIT();
        }

        for (int kc = 0; kc < 8; kc++) {
            CP_WAIT(1);
            __syncthreads();
            if (kc + 2 < 8) {
                const int s = (kc + 2) % 3;
#pragma unroll
                for (int i = 0; i < 8; i++) {
                    int idx = tid + i * 256;
                    int row = idx >> 5, seg = (idx & 31) * 8;
                    CP16(sb + PS_B_OFF + s * PS_B_STAGE + (row * PS_B_STRIDE + seg) * 2,
                         hsrc + (size_t)row * K2 + (kc + 2) * 256 + seg);
                }
            }
            CP_COMMIT();

            const uint32_t stB = (uint32_t)((kc % 3) * PS_B_STAGE);
            const uint32_t kA  = (uint32_t)((kc & 3) * 256) * 2;
#pragma unroll
            for (int s4 = 0; s4 < 16; s4++) {
                uint32_t a0, a1, a2, a3;
                LDSM4(a0, a1, a2, a3, aBase + kA + s4 * 32);
                uint32_t b0, b1, b2, b3;
                LDSM4(b0, b1, b2, b3, bBase + stB + s4 * 32);
                MMAH(acc[0], a0, a1, a2, a3, b0, b2);
                MMAH(acc[1], a0, a1, a2, a3, b1, b3);
            }
        }

        // ---- z = acc + pre -> zbuf ----
        zbuf[R1 * 66 + col0]           = acc[0][0] + p00.x;
        zbuf[R1 * 66 + col0 + 1]       = acc[0][1] + p00.y;
        zbuf[(R1 + 8) * 66 + col0]     = acc[0][2] + p01.x;
        zbuf[(R1 + 8) * 66 + col0 + 1] = acc[0][3] + p01.y;
        zbuf[R1 * 66 + col1]           = acc[1][0] + p10.x;
        zbuf[R1 * 66 + col1 + 1]       = acc[1][1] + p10.y;
        zbuf[(R1 + 8) * 66 + col1]     = acc[1][2] + p11.x;
        zbuf[(R1 + 8) * 66 + col1 + 1] = acc[1][3] + p11.y;
        __syncthreads();

        // ---- gate pass: 2 cells per thread, c in registers ----
        float hval[2], cval[2];
        int jidx[2];
#pragma unroll
        for (int q = 0; q < 2; q++) {
            const int jl = jp * 2 + q;
            const int j  = (r0 >> 2) + jl;
            jidx[q] = j;
            float zf = zbuf[(jl * 4 + 0) * 66 + cb];
            float zi = zbuf[(jl * 4 + 1) * 66 + cb];
            float zg = zbuf[(jl * 4 + 2) * 66 + cb];
            float zo = zbuf[(jl * 4 + 3) * 66 + cb];
            float f  = sigf(zf);
            float ig = sigf(zi);
            float gg = tanhfast(zg);
            float oo = sigf(zo);
            float cprev = q ? creg1 : creg0;
            float cn = f * cprev + ig * gg;
            if (q) creg1 = cn; else creg0 = cn;
            float h = oo * tanhfast(cn);
            hval[q] = h; cval[q] = cn;
            __half hh = __float2half(h);
            __half hl = __float2half(h - __half2float(hh));
            hdst[(size_t)cb * K2 + j]        = hh;
            hdst[(size_t)cb * K2 + 1024 + j] = hl;
        }

        // ---- arrive, then off-critical-path stores, then wait ----
        __threadfence();
        __syncthreads();
        if (tid == 0) atomicAdd(&g_sync, 1);

        float* out_t = out + (size_t)t * BATCH * DH;
#pragma unroll
        for (int q = 0; q < 2; q++) {
            out_t[(size_t)cb * DH + jidx[q]] = hval[q];
            if (t == SEQ - 1) {
                const size_t outs = (size_t)SEQ * BATCH * DH;
                out[outs + (size_t)cb * DH + jidx[q]] = hval[q];                 // h_n
                out[outs + BATCH * DH + (size_t)cb * DH + jidx[q]] = cval[q];    // c_n
            }
        }

        if (tid == 0) {
            const int target = 128 * (t + 1);
            while (*(volatile int*)&g_sync < target) {}
            __threadfence();
        }
        __syncthreads();
    }
}

// ---------------- launch ----------------
extern "C" void kernel_launch(void* const* d_in, const int* in_sizes, int n_in,
                              void* d_out, int out_size) {
    const float* X  = (const float*)d_in[0];
    const float* Wf = (const float*)d_in[1];
    const float* bf = (const float*)d_in[2];
    const float* Wi = (const float*)d_in[3];
    const float* bi = (const float*)d_in[4];
    const float* Wg = (const float*)d_in[5];
    const float* bg = (const float*)d_in[6];
    const float* Wo = (const float*)d_in[7];
    const float* bo = (const float*)d_in[8];
    float* out = (float*)d_out;

    static int attr_done = 0;
    if (!attr_done) {
        cudaFuncSetAttribute(xproj_kernel, cudaFuncAttributeMaxDynamicSharedMemorySize, XP_SMEM);
        cudaFuncSetAttribute(persistent_kernel, cudaFuncAttributeMaxDynamicSharedMemorySize, PS_SMEM);
        attr_done = 1;
    }

    prep_kernel<<<2048, 256>>>(Wf, bf, Wi, bi, Wg, bg, Wo, bo);
    xsplit_kernel<<<4096, 256>>>(X);

    dim3 gx(32, 256);
    xproj_kernel<<<gx, 256, XP_SMEM>>>();

    persistent_kernel<<<128, 256, PS_SMEM>>>(out);
}

// round 8
// speedup vs baseline: 5.5220x; 1.2769x over previous
#include <cuda_runtime.h>
#include <cuda_fp16.h>
#include <stdint.h>

// ---------------- problem constants ----------------
#define SEQ   512
#define BATCH 64
#define DIN   1024
#define DH    1024
#define NG    4096            // 4 gates * DH, reordered r = j*4 + g
#define K2    2048            // xproj: B = [xh | xl] fp16 exact split
#define MTOT  (SEQ * BATCH)

// ---------------- device scratch ----------------
__device__ __align__(16) __half g_Wxf[(size_t)NG * 1024];    // 8.4 MB fp16
__device__ __align__(16) __half g_Whf[(size_t)NG * 1024];    // 8.4 MB fp16
__device__ __align__(16) __half g_Xs2[(size_t)MTOT * K2];    // 128 MB [xh|xl]
__device__ __align__(16) __half g_hs[2][BATCH * 1024];       // h fp16 ping-pong (unsplit)
__device__ float g_bias[NG];
__device__ float g_pre[(size_t)SEQ * NG * BATCH];            // 512 MB pre[t][r][b]
__device__ int   g_sync;                                     // step barrier

// ---------------- asm helpers (baseline PTX only) ----------------
__device__ __forceinline__ uint32_t smem_u32(const void* p) {
    uint32_t a;
    asm("{ .reg .u64 t; cvta.to.shared.u64 t, %1; cvt.u32.u64 %0, t; }" : "=r"(a) : "l"(p));
    return a;
}
#define CP16(dst, src) asm volatile("cp.async.cg.shared.global [%0], [%1], 16;" :: "r"(dst), "l"(src))
#define CP_COMMIT()    asm volatile("cp.async.commit_group;" ::: "memory")
#define CP_WAIT(n)     asm volatile("cp.async.wait_group %0;" :: "n"(n) : "memory")

#define LDSM4(r0, r1, r2, r3, a) \
    asm volatile("ldmatrix.sync.aligned.m8n8.x4.shared.b16 {%0,%1,%2,%3}, [%4];" \
                 : "=r"(r0), "=r"(r1), "=r"(r2), "=r"(r3) : "r"(a))

#define MMAH(d, a0, a1, a2, a3, b0, b1) \
    asm volatile("mma.sync.aligned.m16n8k16.row.col.f32.f16.f16.f32 " \
                 "{%0,%1,%2,%3}, {%4,%5,%6,%7}, {%8,%9}, {%0,%1,%2,%3};" \
                 : "+f"((d)[0]), "+f"((d)[1]), "+f"((d)[2]), "+f"((d)[3]) \
                 : "r"(a0), "r"(a1), "r"(a2), "r"(a3), "r"(b0), "r"(b1))

__device__ __forceinline__ float sigf(float x) { return 1.0f / (1.0f + __expf(-x)); }
__device__ __forceinline__ float tanhfast(float x) { return 1.0f - 2.0f / (__expf(2.0f * x) + 1.0f); }

// ---------------- prep: weights -> fp16, bias, zero states ----------------
__global__ void prep_kernel(const float* __restrict__ Wf, const float* __restrict__ bf,
                            const float* __restrict__ Wi, const float* __restrict__ bi,
                            const float* __restrict__ Wg, const float* __restrict__ bg,
                            const float* __restrict__ Wo, const float* __restrict__ bo) {
    int idx = blockIdx.x * blockDim.x + threadIdx.x;
    int stride = gridDim.x * blockDim.x;
    if (idx == 0) g_sync = 0;
    for (int i = idx; i < NG * 512; i += stride) {
        int r = i >> 9;
        int k4 = (i & 511) * 4;
        int j = r >> 2, g = r & 3;
        const float* W = (g == 0) ? Wf : (g == 1) ? Wi : (g == 2) ? Wg : Wo;
        float4 v = *(const float4*)(W + (size_t)j * 2048 + k4);
        union { __half h[4]; uint2 u; } h4;
        h4.h[0] = __float2half(v.x); h4.h[1] = __float2half(v.y);
        h4.h[2] = __float2half(v.z); h4.h[3] = __float2half(v.w);
        if (k4 < 1024) *(uint2*)(g_Wxf + (size_t)r * 1024 + k4)          = h4.u;
        else           *(uint2*)(g_Whf + (size_t)r * 1024 + (k4 - 1024)) = h4.u;
    }
    for (int i = idx; i < NG; i += stride) {
        int j = i >> 2, g = i & 3;
        const float* b = (g == 0) ? bf : (g == 1) ? bi : (g == 2) ? bg : bo;
        g_bias[i] = b[j];
    }
    for (int i = idx; i < BATCH * 1024; i += stride) {
        g_hs[0][i] = __float2half(0.0f);
        g_hs[1][i] = __float2half(0.0f);
    }
}

// ---------------- X -> exact fp16 split [xh | xl] ----------------
__global__ void xsplit_kernel(const float* __restrict__ X) {
    int idx = blockIdx.x * blockDim.x + threadIdx.x;
    int stride = gridDim.x * blockDim.x;
    for (int i = idx; i < MTOT * 256; i += stride) {
        int m = i >> 8;
        int k4 = (i & 255) * 4;
        float4 v = *(const float4*)(X + (size_t)m * DIN + k4);
        float vv[4] = {v.x, v.y, v.z, v.w};
        union { __half h[4]; uint2 u; } hi4, lo4;
#pragma unroll
        for (int q = 0; q < 4; q++) {
            __half h = __float2half(vv[q]);
            hi4.h[q] = h;
            lo4.h[q] = __float2half(vv[q] - __half2float(h));
        }
        __half* row = g_Xs2 + (size_t)m * K2;
        *(uint2*)(row + k4)        = hi4.u;
        *(uint2*)(row + 1024 + k4) = lo4.u;
    }
}

// ============================================================
// xproj (unchanged from R7, verified): pre[t][r][b] = Wxf . [xh|xl]^T + bias
// ============================================================
#define XP_STAGE 18432
#define XP_SMEM  (3 * XP_STAGE * 2)

__global__ __launch_bounds__(256, 1) void xproj_kernel() {
    extern __shared__ __half smem[];
    const uint32_t sb = smem_u32(smem);
    const int tid  = threadIdx.x;
    const int lane = tid & 31;
    const int wid  = tid >> 5;
    const int wm   = wid & 3;
    const int wn   = wid >> 2;
    const int r0   = blockIdx.x * 128;
    const int tok0 = blockIdx.y * 128;

    const int lrow = tid >> 3;
    const int lseg = (tid & 7) * 8;

    const uint32_t aBase = sb + ((wm * 32 + (lane & 15)) * 72 + ((lane >> 4) * 8)) * 2;
    const uint32_t bBase = sb + (9216 + (wn * 64 + (lane & 15)) * 72 + ((lane >> 4) * 8)) * 2;

    float acc[2][8][4];
#pragma unroll
    for (int i = 0; i < 2; i++)
#pragma unroll
        for (int n = 0; n < 8; n++)
#pragma unroll
            for (int q = 0; q < 4; q++) acc[i][n][q] = 0.0f;

    const int NC = 32;
#pragma unroll
    for (int s = 0; s < 2; s++) {
        const int kb = s * 64;
#pragma unroll
        for (int j = 0; j < 4; j++) {
            int row = lrow + j * 32;
            CP16(sb + (s * XP_STAGE + row * 72 + lseg) * 2,
                 g_Wxf + (size_t)(r0 + row) * 1024 + (kb & 1023) + lseg);
            CP16(sb + (s * XP_STAGE + 9216 + row * 72 + lseg) * 2,
                 g_Xs2 + (size_t)(tok0 + row) * K2 + kb + lseg);
        }
        CP_COMMIT();
    }

    for (int c = 0; c < NC; c++) {
        CP_WAIT(1);
        __syncthreads();
        if (c + 2 < NC) {
            const int s = (c + 2) % 3;
            const int kb = (c + 2) * 64;
#pragma unroll
            for (int j = 0; j < 4; j++) {
                int row = lrow + j * 32;
                CP16(sb + (s * XP_STAGE + row * 72 + lseg) * 2,
                     g_Wxf + (size_t)(r0 + row) * 1024 + (kb & 1023) + lseg);
                CP16(sb + (s * XP_STAGE + 9216 + row * 72 + lseg) * 2,
                     g_Xs2 + (size_t)(tok0 + row) * K2 + kb + lseg);
            }
        }
        CP_COMMIT();

        const uint32_t stOff = (uint32_t)((c % 3) * XP_STAGE) * 2;
#pragma unroll
        for (int s4 = 0; s4 < 4; s4++) {
            const uint32_t kOff = s4 * 32;
            uint32_t a0, a1, a2, a3, a4, a5, a6, a7;
            LDSM4(a0, a1, a2, a3, aBase + stOff + kOff);
            LDSM4(a4, a5, a6, a7, aBase + stOff + kOff + 16 * 144);
#pragma unroll
            for (int g = 0; g < 4; g++) {
                uint32_t b0, b1, b2, b3;
                LDSM4(b0, b1, b2, b3, bBase + stOff + kOff + g * 16 * 144);
                MMAH(acc[0][2 * g],     a0, a1, a2, a3, b0, b2);
                MMAH(acc[0][2 * g + 1], a0, a1, a2, a3, b1, b3);
                MMAH(acc[1][2 * g],     a4, a5, a6, a7, b0, b2);
                MMAH(acc[1][2 * g + 1], a4, a5, a6, a7, b1, b3);
            }
        }
    }
    CP_WAIT(0);

    const int gq = lane >> 2;
    const int t4 = lane & 3;
#pragma unroll
    for (int mi = 0; mi < 2; mi++) {
        const int R = r0 + wm * 32 + mi * 16 + gq;
        const float bias0 = g_bias[R];
        const float bias8 = g_bias[R + 8];
#pragma unroll
        for (int nb = 0; nb < 8; nb++) {
            const int n = wn * 64 + nb * 8 + t4 * 2;
            const int token = tok0 + n;
            const int tt = token >> 6;
            const int bb = token & 63;
            float* p0 = g_pre + ((size_t)tt * NG + R) * 64 + bb;
            *(float2*)p0 = make_float2(acc[mi][nb][0] + bias0, acc[mi][nb][1] + bias0);
            *(float2*)(p0 + 8 * 64) = make_float2(acc[mi][nb][2] + bias8, acc[mi][nb][3] + bias8);
        }
    }
}

// ============================================================
// persistent recurrence: 128 CTAs x 256 thr, all 512 steps.
// CTA: M=32 gate rows, N=64 batch, K=1024 (h unsplit fp16).
// A = Whf panel (32x1024) resident.  B = h (64x1024) in 2 chunks of 512,
// both double-buffered in smem -> only 2 mainloop iterations per step.
// ============================================================
#define PS_A_STRIDE 1032
#define PS_A_BYTES  (32 * PS_A_STRIDE * 2)            // 66048
#define PS_B_STRIDE 520
#define PS_B_STAGE  (64 * PS_B_STRIDE * 2)            // 66560
#define PS_B_OFF    PS_A_BYTES
#define PS_ZB_OFF   (PS_A_BYTES + 2 * PS_B_STAGE)     // 199168
#define PS_SMEM     (PS_ZB_OFF + 32 * 66 * 4)         // 207616

__global__ __launch_bounds__(256, 1) void persistent_kernel(float* __restrict__ out) {
    extern __shared__ __half smem[];
    const uint32_t sb = smem_u32(smem);
    const int tid  = threadIdx.x;
    const int lane = tid & 31;
    const int wid  = tid >> 5;
    const int wm   = wid & 1;               // m block of 16
    const int wn   = wid >> 1;              // n block of 16
    const int r0   = blockIdx.x * 32;

    // ---- A panel resident: 32 rows x 1024 fp16 ----
    for (int i = tid; i < 32 * 128; i += 256) {
        int row = i >> 7;
        int seg = (i & 127) * 8;
        uint4 v = *(const uint4*)(g_Whf + (size_t)(r0 + row) * 1024 + seg);
        *(uint4*)((char*)smem + (row * PS_A_STRIDE + seg) * 2) = v;
    }
    __syncthreads();

    const uint32_t aBase = sb + ((wm * 16 + (lane & 15)) * PS_A_STRIDE + (lane >> 4) * 8) * 2;
    const uint32_t bBase = sb + PS_B_OFF + ((wn * 16 + (lane & 15)) * PS_B_STRIDE + (lane >> 4) * 8) * 2;
    float* zbuf = (float*)((char*)smem + PS_ZB_OFF);

    const int gq  = lane >> 2;
    const int t4  = lane & 3;
    const int R1  = wm * 16 + gq;
    const int col0 = wn * 16 + t4 * 2;
    const int col1 = wn * 16 + 8 + t4 * 2;
    const int cb  = tid >> 2;
    const int jp  = tid & 3;
    float creg0 = 0.0f, creg1 = 0.0f;

    for (int t = 0; t < SEQ; t++) {
        const __half* hsrc = g_hs[t & 1];
        __half* hdst = g_hs[(t + 1) & 1];
        const float* pre_t = g_pre + (size_t)t * NG * 64;

        // ---- issue both B chunks immediately (separate commit groups) ----
#pragma unroll
        for (int s = 0; s < 2; s++) {
#pragma unroll
            for (int i = 0; i < 16; i++) {
                int idx = tid + i * 256;
                int row = idx >> 6, seg = (idx & 63) * 8;
                CP16(sb + PS_B_OFF + s * PS_B_STAGE + (row * PS_B_STRIDE + seg) * 2,
                     hsrc + (size_t)row * 1024 + s * 512 + seg);
            }
            CP_COMMIT();
        }

        // prefetch pre for this CTA's tile (consumed post-mainloop)
        float2 p00 = *(const float2*)(pre_t + (size_t)(r0 + R1) * 64 + col0);
        float2 p01 = *(const float2*)(pre_t + (size_t)(r0 + R1 + 8) * 64 + col0);
        float2 p10 = *(const float2*)(pre_t + (size_t)(r0 + R1) * 64 + col1);
        float2 p11 = *(const float2*)(pre_t + (size_t)(r0 + R1 + 8) * 64 + col1);

        float acc[2][4];
#pragma unroll
        for (int n = 0; n < 2; n++)
#pragma unroll
            for (int q = 0; q < 4; q++) acc[n][q] = 0.0f;

#pragma unroll
        for (int kc = 0; kc < 2; kc++) {
            if (kc == 0) CP_WAIT(1); else CP_WAIT(0);
            __syncthreads();
            const uint32_t stB = (uint32_t)(kc * PS_B_STAGE);
            const uint32_t kA  = (uint32_t)(kc * 512) * 2;
#pragma unroll
            for (int s4 = 0; s4 < 32; s4++) {
                uint32_t a0, a1, a2, a3;
                LDSM4(a0, a1, a2, a3, aBase + kA + s4 * 32);
                uint32_t b0, b1, b2, b3;
                LDSM4(b0, b1, b2, b3, bBase + stB + s4 * 32);
                MMAH(acc[0], a0, a1, a2, a3, b0, b2);
                MMAH(acc[1], a0, a1, a2, a3, b1, b3);
            }
        }

        // ---- z = acc + pre -> zbuf ----
        __syncthreads();   // B smem reuse-safe (zbuf is separate; protects zbuf from prev step)
        zbuf[R1 * 66 + col0]           = acc[0][0] + p00.x;
        zbuf[R1 * 66 + col0 + 1]       = acc[0][1] + p00.y;
        zbuf[(R1 + 8) * 66 + col0]     = acc[0][2] + p01.x;
        zbuf[(R1 + 8) * 66 + col0 + 1] = acc[0][3] + p01.y;
        zbuf[R1 * 66 + col1]           = acc[1][0] + p10.x;
        zbuf[R1 * 66 + col1 + 1]       = acc[1][1] + p10.y;
        zbuf[(R1 + 8) * 66 + col1]     = acc[1][2] + p11.x;
        zbuf[(R1 + 8) * 66 + col1 + 1] = acc[1][3] + p11.y;
        __syncthreads();

        // ---- gate pass: 2 cells per thread, c in registers ----
        float hval[2], cval[2];
        int jidx[2];
#pragma unroll
        for (int q = 0; q < 2; q++) {
            const int jl = jp * 2 + q;
            const int j  = (r0 >> 2) + jl;
            jidx[q] = j;
            float zf = zbuf[(jl * 4 + 0) * 66 + cb];
            float zi = zbuf[(jl * 4 + 1) * 66 + cb];
            float zg = zbuf[(jl * 4 + 2) * 66 + cb];
            float zo = zbuf[(jl * 4 + 3) * 66 + cb];
            float f  = sigf(zf);
            float ig = sigf(zi);
            float gg = tanhfast(zg);
            float oo = sigf(zo);
            float cprev = q ? creg1 : creg0;
            float cn = f * cprev + ig * gg;
            if (q) creg1 = cn; else creg0 = cn;
            float h = oo * tanhfast(cn);
            hval[q] = h; cval[q] = cn;
            hdst[(size_t)cb * 1024 + j] = __float2half(h);
        }

        // ---- arrive, then off-critical-path stores, then wait ----
        __threadfence();
        __syncthreads();
        if (tid == 0) atomicAdd(&g_sync, 1);

        float* out_t = out + (size_t)t * BATCH * DH;
#pragma unroll
        for (int q = 0; q < 2; q++) {
            out_t[(size_t)cb * DH + jidx[q]] = hval[q];
            if (t == SEQ - 1) {
                const size_t outs = (size_t)SEQ * BATCH * DH;
                out[outs + (size_t)cb * DH + jidx[q]] = hval[q];                 // h_n
                out[outs + BATCH * DH + (size_t)cb * DH + jidx[q]] = cval[q];    // c_n
            }
        }

        if (tid == 0) {
            const int target = 128 * (t + 1);
            while (*(volatile int*)&g_sync < target) {}
            __threadfence();
        }
        __syncthreads();
    }
}

// ---------------- launch ----------------
extern "C" void kernel_launch(void* const* d_in, const int* in_sizes, int n_in,
                              void* d_out, int out_size) {
    const float* X  = (const float*)d_in[0];
    const float* Wf = (const float*)d_in[1];
    const float* bf = (const float*)d_in[2];
    const float* Wi = (const float*)d_in[3];
    const float* bi = (const float*)d_in[4];
    const float* Wg = (const float*)d_in[5];
    const float* bg = (const float*)d_in[6];
    const float* Wo = (const float*)d_in[7];
    const float* bo = (const float*)d_in[8];
    float* out = (float*)d_out;

    static int attr_done = 0;
    if (!attr_done) {
        cudaFuncSetAttribute(xproj_kernel, cudaFuncAttributeMaxDynamicSharedMemorySize, XP_SMEM);
        cudaFuncSetAttribute(persistent_kernel, cudaFuncAttributeMaxDynamicSharedMemorySize, PS_SMEM);
        attr_done = 1;
    }

    prep_kernel<<<2048, 256>>>(Wf, bf, Wi, bi, Wg, bg, Wo, bo);
    xsplit_kernel<<<4096, 256>>>(X);

    dim3 gx(32, 256);
    xproj_kernel<<<gx, 256, XP_SMEM>>>();

    persistent_kernel<<<128, 256, PS_SMEM>>>(out);
}

// round 10
// speedup vs baseline: 6.7580x; 1.2238x over previous
#include <cuda_runtime.h>
#include <cuda_fp16.h>
#include <stdint.h>

// ---------------- problem constants ----------------
#define SEQ   512
#define BATCH 64
#define DIN   1024
#define DH    1024
#define NG    4096            // 4 gates * DH, reordered r = j*4 + g
#define MTOT  (SEQ * BATCH)

// ---------------- device scratch ----------------
__device__ __align__(16) __half g_Wxf[(size_t)NG * 1024];    // 8.4 MB fp16
__device__ __align__(16) __half g_Whf[(size_t)NG * 1024];    // 8.4 MB fp16
__device__ __align__(16) __half g_Xsf[(size_t)MTOT * 1024];  // 64 MB  x fp16 (unsplit)
__device__ __align__(16) __half g_hs[2][BATCH * 1024];       // h fp16 ping-pong
__device__ float g_bias[NG];
__device__ float g_pre[(size_t)SEQ * NG * BATCH];            // 512 MB pre[t][r][b]
__device__ int   g_sync;                                     // step barrier

// ---------------- asm helpers (baseline PTX only) ----------------
__device__ __forceinline__ uint32_t smem_u32(const void* p) {
    uint32_t a;
    asm("{ .reg .u64 t; cvta.to.shared.u64 t, %1; cvt.u32.u64 %0, t; }" : "=r"(a) : "l"(p));
    return a;
}
#define CP16(dst, src) asm volatile("cp.async.cg.shared.global [%0], [%1], 16;" :: "r"(dst), "l"(src))
#define CP_COMMIT()    asm volatile("cp.async.commit_group;" ::: "memory")
#define CP_WAIT(n)     asm volatile("cp.async.wait_group %0;" :: "n"(n) : "memory")

#define LDSM4(r0, r1, r2, r3, a) \
    asm volatile("ldmatrix.sync.aligned.m8n8.x4.shared.b16 {%0,%1,%2,%3}, [%4];" \
                 : "=r"(r0), "=r"(r1), "=r"(r2), "=r"(r3) : "r"(a))

#define MMAH(d, a0, a1, a2, a3, b0, b1) \
    asm volatile("mma.sync.aligned.m16n8k16.row.col.f32.f16.f16.f32 " \
                 "{%0,%1,%2,%3}, {%4,%5,%6,%7}, {%8,%9}, {%0,%1,%2,%3};" \
                 : "+f"((d)[0]), "+f"((d)[1]), "+f"((d)[2]), "+f"((d)[3]) \
                 : "r"(a0), "r"(a1), "r"(a2), "r"(a3), "r"(b0), "r"(b1))

__device__ __forceinline__ float sigf(float x) { return 1.0f / (1.0f + __expf(-x)); }
__device__ __forceinline__ float tanhfast(float x) { return 1.0f - 2.0f / (__expf(2.0f * x) + 1.0f); }

// ---------------- prep: weights + X -> fp16, bias, zero states ----------------
__global__ void prep_kernel(const float* __restrict__ X,
                            const float* __restrict__ Wf, const float* __restrict__ bf,
                            const float* __restrict__ Wi, const float* __restrict__ bi,
                            const float* __restrict__ Wg, const float* __restrict__ bg,
                            const float* __restrict__ Wo, const float* __restrict__ bo) {
    int idx = blockIdx.x * blockDim.x + threadIdx.x;
    int stride = gridDim.x * blockDim.x;
    if (idx == 0) g_sync = 0;
    // weights
    for (int i = idx; i < NG * 512; i += stride) {
        int r = i >> 9;
        int k4 = (i & 511) * 4;
        int j = r >> 2, g = r & 3;
        const float* W = (g == 0) ? Wf : (g == 1) ? Wi : (g == 2) ? Wg : Wo;
        float4 v = *(const float4*)(W + (size_t)j * 2048 + k4);
        union { __half h[4]; uint2 u; } h4;
        h4.h[0] = __float2half(v.x); h4.h[1] = __float2half(v.y);
        h4.h[2] = __float2half(v.z); h4.h[3] = __float2half(v.w);
        if (k4 < 1024) *(uint2*)(g_Wxf + (size_t)r * 1024 + k4)          = h4.u;
        else           *(uint2*)(g_Whf + (size_t)r * 1024 + (k4 - 1024)) = h4.u;
    }
    // X -> fp16
    for (int i = idx; i < MTOT * 256; i += stride) {
        float4 v = *(const float4*)(X + (size_t)i * 4);
        union { __half h[4]; uint2 u; } h4;
        h4.h[0] = __float2half(v.x); h4.h[1] = __float2half(v.y);
        h4.h[2] = __float2half(v.z); h4.h[3] = __float2half(v.w);
        *(uint2*)(g_Xsf + (size_t)i * 4) = h4.u;
    }
    for (int i = idx; i < NG; i += stride) {
        int j = i >> 2, g = i & 3;
        const float* b = (g == 0) ? bf : (g == 1) ? bi : (g == 2) ? bg : bo;
        g_bias[i] = b[j];
    }
    for (int i = idx; i < BATCH * 1024; i += stride) {
        g_hs[0][i] = __float2half(0.0f);
        g_hs[1][i] = __float2half(0.0f);
    }
}

// ============================================================
// xproj: pre[t][r][b] = Wxf . x^T + bias   (K=1024, fp16)
// CTA tile 128 gates x 128 tokens, 8 warps (m32 x n64), k=64 chunks (NC=16).
// ============================================================
#define XP_STAGE 18432
#define XP_SMEM  (3 * XP_STAGE * 2)

__global__ __launch_bounds__(256, 1) void xproj_kernel() {
    extern __shared__ __half smem[];
    const uint32_t sb = smem_u32(smem);
    const int tid  = threadIdx.x;
    const int lane = tid & 31;
    const int wid  = tid >> 5;
    const int wm   = wid & 3;
    const int wn   = wid >> 2;
    const int r0   = blockIdx.x * 128;
    const int tok0 = blockIdx.y * 128;

    const int lrow = tid >> 3;
    const int lseg = (tid & 7) * 8;

    const uint32_t aBase = sb + ((wm * 32 + (lane & 15)) * 72 + ((lane >> 4) * 8)) * 2;
    const uint32_t bBase = sb + (9216 + (wn * 64 + (lane & 15)) * 72 + ((lane >> 4) * 8)) * 2;

    float acc[2][8][4];
#pragma unroll
    for (int i = 0; i < 2; i++)
#pragma unroll
        for (int n = 0; n < 8; n++)
#pragma unroll
            for (int q = 0; q < 4; q++) acc[i][n][q] = 0.0f;

    const int NC = 16;
#pragma unroll
    for (int s = 0; s < 2; s++) {
        const int kb = s * 64;
#pragma unroll
        for (int j = 0; j < 4; j++) {
            int row = lrow + j * 32;
            CP16(sb + (s * XP_STAGE + row * 72 + lseg) * 2,
                 g_Wxf + (size_t)(r0 + row) * 1024 + kb + lseg);
            CP16(sb + (s * XP_STAGE + 9216 + row * 72 + lseg) * 2,
                 g_Xsf + (size_t)(tok0 + row) * 1024 + kb + lseg);
        }
        CP_COMMIT();
    }

    for (int c = 0; c < NC; c++) {
        CP_WAIT(1);
        __syncthreads();
        if (c + 2 < NC) {
            const int s = (c + 2) % 3;
            const int kb = (c + 2) * 64;
#pragma unroll
            for (int j = 0; j < 4; j++) {
                int row = lrow + j * 32;
                CP16(sb + (s * XP_STAGE + row * 72 + lseg) * 2,
                     g_Wxf + (size_t)(r0 + row) * 1024 + kb + lseg);
                CP16(sb + (s * XP_STAGE + 9216 + row * 72 + lseg) * 2,
                     g_Xsf + (size_t)(tok0 + row) * 1024 + kb + lseg);
            }
        }
        CP_COMMIT();

        const uint32_t stOff = (uint32_t)((c % 3) * XP_STAGE) * 2;
#pragma unroll
        for (int s4 = 0; s4 < 4; s4++) {
            const uint32_t kOff = s4 * 32;
            uint32_t a0, a1, a2, a3, a4, a5, a6, a7;
            LDSM4(a0, a1, a2, a3, aBase + stOff + kOff);
            LDSM4(a4, a5, a6, a7, aBase + stOff + kOff + 16 * 144);
#pragma unroll
            for (int g = 0; g < 4; g++) {
                uint32_t b0, b1, b2, b3;
                LDSM4(b0, b1, b2, b3, bBase + stOff + kOff + g * 16 * 144);
                MMAH(acc[0][2 * g],     a0, a1, a2, a3, b0, b2);
                MMAH(acc[0][2 * g + 1], a0, a1, a2, a3, b1, b3);
                MMAH(acc[1][2 * g],     a4, a5, a6, a7, b0, b2);
                MMAH(acc[1][2 * g + 1], a4, a5, a6, a7, b1, b3);
            }
        }
    }
    CP_WAIT(0);

    const int gq = lane >> 2;
    const int t4 = lane & 3;
#pragma unroll
    for (int mi = 0; mi < 2; mi++) {
        const int R = r0 + wm * 32 + mi * 16 + gq;
        const float bias0 = g_bias[R];
        const float bias8 = g_bias[R + 8];
#pragma unroll
        for (int nb = 0; nb < 8; nb++) {
            const int n = wn * 64 + nb * 8 + t4 * 2;
            const int token = tok0 + n;
            const int tt = token >> 6;
            const int bb = token & 63;
            float* p0 = g_pre + ((size_t)tt * NG + R) * 64 + bb;
            *(float2*)p0 = make_float2(acc[mi][nb][0] + bias0, acc[mi][nb][1] + bias0);
            *(float2*)(p0 + 8 * 64) = make_float2(acc[mi][nb][2] + bias8, acc[mi][nb][3] + bias8);
        }
    }
}

// ============================================================
// persistent recurrence: 128 CTAs x 256 thr, all 512 steps.
// CTA: M=32 gate rows, N=64 batch, K=1024.
// A = Whf panel (32x1024) resident. B = h in 4 chunks of 256, 3-stage.
// Each chunk = 64 rows x 32 uint4 = 2048 CP16s -> 8 per thread.
// ============================================================
#define PS_A_STRIDE 1032
#define PS_A_BYTES  (32 * PS_A_STRIDE * 2)            // 66048
#define PS_B_STRIDE 264
#define PS_B_STAGE  (64 * PS_B_STRIDE * 2)            // 33792
#define PS_B_OFF    PS_A_BYTES
#define PS_ZB_OFF   (PS_A_BYTES + 3 * PS_B_STAGE)     // 167424
#define PS_SMEM     (PS_ZB_OFF + 32 * 66 * 4)         // 175872

__global__ __launch_bounds__(256, 1) void persistent_kernel(float* __restrict__ out) {
    extern __shared__ __half smem[];
    const uint32_t sb = smem_u32(smem);
    const int tid  = threadIdx.x;
    const int lane = tid & 31;
    const int wid  = tid >> 5;
    const int wm   = wid & 1;               // m block of 16
    const int wn   = wid >> 1;              // n block of 16
    const int r0   = blockIdx.x * 32;

    // ---- A panel resident: 32 rows x 1024 fp16 ----
    for (int i = tid; i < 32 * 128; i += 256) {
        int row = i >> 7;
        int seg = (i & 127) * 8;
        uint4 v = *(const uint4*)(g_Whf + (size_t)(r0 + row) * 1024 + seg);
        *(uint4*)((char*)smem + (row * PS_A_STRIDE + seg) * 2) = v;
    }
    __syncthreads();

    const uint32_t aBase = sb + ((wm * 16 + (lane & 15)) * PS_A_STRIDE + (lane >> 4) * 8) * 2;
    const uint32_t bBase = sb + PS_B_OFF + ((wn * 16 + (lane & 15)) * PS_B_STRIDE + (lane >> 4) * 8) * 2;
    float* zbuf = (float*)((char*)smem + PS_ZB_OFF);

    const int gq  = lane >> 2;
    const int t4  = lane & 3;
    const int R1  = wm * 16 + gq;
    const int col0 = wn * 16 + t4 * 2;
    const int col1 = wn * 16 + 8 + t4 * 2;
    const int cb  = tid >> 2;
    const int jp  = tid & 3;
    float creg0 = 0.0f, creg1 = 0.0f;

    for (int t = 0; t < SEQ; t++) {
        const __half* hsrc = g_hs[t & 1];
        __half* hdst = g_hs[(t + 1) & 1];
        const float* pre_t = g_pre + (size_t)t * NG * 64;

        // prologue: chunks 0,1  (2048 CP16 per chunk -> 8 per thread)
#pragma unroll
        for (int s = 0; s < 2; s++) {
#pragma unroll
            for (int i = 0; i < 8; i++) {
                int idx = tid + i * 256;                 // 0..2047
                int row = idx >> 5;                      // 0..63
                int seg = (idx & 31) * 8;                // 0..248
                CP16(sb + PS_B_OFF + s * PS_B_STAGE + (row * PS_B_STRIDE + seg) * 2,
                     hsrc + (size_t)row * 1024 + s * 256 + seg);
            }
            CP_COMMIT();
        }

        // prefetch pre for this CTA's tile (consumed post-mainloop)
        float2 p00 = *(const float2*)(pre_t + (size_t)(r0 + R1) * 64 + col0);
        float2 p01 = *(const float2*)(pre_t + (size_t)(r0 + R1 + 8) * 64 + col0);
        float2 p10 = *(const float2*)(pre_t + (size_t)(r0 + R1) * 64 + col1);
        float2 p11 = *(const float2*)(pre_t + (size_t)(r0 + R1 + 8) * 64 + col1);

        float acc[2][4];
#pragma unroll
        for (int n = 0; n < 2; n++)
#pragma unroll
            for (int q = 0; q < 4; q++) acc[n][q] = 0.0f;

#pragma unroll
        for (int kc = 0; kc < 4; kc++) {
            CP_WAIT(1);
            __syncthreads();
            if (kc + 2 < 4) {
                const int s = (kc + 2) % 3;
#pragma unroll
                for (int i = 0; i < 8; i++) {
                    int idx = tid + i * 256;
                    int row = idx >> 5;
                    int seg = (idx & 31) * 8;
                    CP16(sb + PS_B_OFF + s * PS_B_STAGE + (row * PS_B_STRIDE + seg) * 2,
                         hsrc + (size_t)row * 1024 + (kc + 2) * 256 + seg);
                }
            }
            CP_COMMIT();

            const uint32_t stB = (uint32_t)((kc % 3) * PS_B_STAGE);
            const uint32_t kA  = (uint32_t)(kc * 512);          // 256 elems * 2 bytes
#pragma unroll
            for (int s4 = 0; s4 < 16; s4++) {
                uint32_t a0, a1, a2, a3;
                LDSM4(a0, a1, a2, a3, aBase + kA + s4 * 32);
                uint32_t b0, b1, b2, b3;
                LDSM4(b0, b1, b2, b3, bBase + stB + s4 * 32);
                MMAH(acc[0], a0, a1, a2, a3, b0, b2);
                MMAH(acc[1], a0, a1, a2, a3, b1, b3);
            }
        }

        // ---- z = acc + pre -> zbuf ----
        zbuf[R1 * 66 + col0]           = acc[0][0] + p00.x;
        zbuf[R1 * 66 + col0 + 1]       = acc[0][1] + p00.y;
        zbuf[(R1 + 8) * 66 + col0]     = acc[0][2] + p01.x;
        zbuf[(R1 + 8) * 66 + col0 + 1] = acc[0][3] + p01.y;
        zbuf[R1 * 66 + col1]           = acc[1][0] + p10.x;
        zbuf[R1 * 66 + col1 + 1]       = acc[1][1] + p10.y;
        zbuf[(R1 + 8) * 66 + col1]     = acc[1][2] + p11.x;
        zbuf[(R1 + 8) * 66 + col1 + 1] = acc[1][3] + p11.y;
        __syncthreads();

        // ---- gate pass: 2 cells per thread, c in registers ----
        float hval[2], cval[2];
        int jidx[2];
#pragma unroll
        for (int q = 0; q < 2; q++) {
            const int jl = jp * 2 + q;
            const int j  = (r0 >> 2) + jl;
            jidx[q] = j;
            float zf = zbuf[(jl * 4 + 0) * 66 + cb];
            float zi = zbuf[(jl * 4 + 1) * 66 + cb];
            float zg = zbuf[(jl * 4 + 2) * 66 + cb];
            float zo = zbuf[(jl * 4 + 3) * 66 + cb];
            float f  = sigf(zf);
            float ig = sigf(zi);
            float gg = tanhfast(zg);
            float oo = sigf(zo);
            float cprev = q ? creg1 : creg0;
            float cn = f * cprev + ig * gg;
            if (q) creg1 = cn; else creg0 = cn;
            float h = oo * tanhfast(cn);
            hval[q] = h; cval[q] = cn;
            hdst[(size_t)cb * 1024 + j] = __float2half(h);
        }

        // ---- arrive, then off-critical-path stores, then wait ----
        __threadfence();
        __syncthreads();
        if (tid == 0) atomicAdd(&g_sync, 1);

        float* out_t = out + (size_t)t * BATCH * DH;
#pragma unroll
        for (int q = 0; q < 2; q++) {
            out_t[(size_t)cb * DH + jidx[q]] = hval[q];
            if (t == SEQ - 1) {
                const size_t outs = (size_t)SEQ * BATCH * DH;
                out[outs + (size_t)cb * DH + jidx[q]] = hval[q];                 // h_n
                out[outs + BATCH * DH + (size_t)cb * DH + jidx[q]] = cval[q];    // c_n
            }
        }

        if (tid == 0) {
            const int target = 128 * (t + 1);
            while (*(volatile int*)&g_sync < target) {}
            __threadfence();
        }
        __syncthreads();
    }
}

// ---------------- launch ----------------
extern "C" void kernel_launch(void* const* d_in, const int* in_sizes, int n_in,
                              void* d_out, int out_size) {
    const float* X  = (const float*)d_in[0];
    const float* Wf = (const float*)d_in[1];
    const float* bf = (const float*)d_in[2];
    const float* Wi = (const float*)d_in[3];
    const float* bi = (const float*)d_in[4];
    const float* Wg = (const float*)d_in[5];
    const float* bg = (const float*)d_in[6];
    const float* Wo = (const float*)d_in[7];
    const float* bo = (const float*)d_in[8];
    float* out = (float*)d_out;

    static int attr_done = 0;
    if (!attr_done) {
        cudaFuncSetAttribute(xproj_kernel, cudaFuncAttributeMaxDynamicSharedMemorySize, XP_SMEM);
        cudaFuncSetAttribute(persistent_kernel, cudaFuncAttributeMaxDynamicSharedMemorySize, PS_SMEM);
        attr_done = 1;
    }

    prep_kernel<<<4096, 256>>>(X, Wf, bf, Wi, bi, Wg, bg, Wo, bo);

    dim3 gx(32, 256);
    xproj_kernel<<<gx, 256, XP_SMEM>>>();

    persistent_kernel<<<128, 256, PS_SMEM>>>(out);
}